// round 11
// baseline (speedup 1.0000x reference)
#include <cuda_runtime.h>
#include <cuda_bf16.h>
#include <math.h>
#include <stdint.h>

// Shapes (fixed by the problem)
#define NB   4
#define CIN  256
#define HH   64
#define WW   64
#define HW   4096
#define CM   64
#define EOUT 100
#define OUTC 256

typedef unsigned long long u64;

// ---- packed fp32x2 helpers (Blackwell FFMA2 via PTX) ----------------------
__device__ __forceinline__ u64 pack2(float lo, float hi) {
    u64 d; asm("mov.b64 %0,{%1,%2};" : "=l"(d) : "f"(lo), "f"(hi)); return d;
}
__device__ __forceinline__ u64 splat2(float v) {
    u64 d; asm("mov.b64 %0,{%1,%1};" : "=l"(d) : "f"(v)); return d;
}
__device__ __forceinline__ void fma2(u64& acc, u64 a, u64 b) {
    asm("fma.rn.f32x2 %0,%1,%2,%0;" : "+l"(acc) : "l"(a), "l"(b));
}
__device__ __forceinline__ float2 unpack2(u64 d) {
    float2 r; asm("mov.b64 {%0,%1},%2;" : "=f"(r.x), "=f"(r.y) : "l"(d)); return r;
}

// Scratch (device globals; allocation is forbidden)
__device__ float g_t[NB * CM * HW];            // 4 MB   down-conv output
__device__ float g_e[NB * EOUT * HW];          // 6.5 MB encoder logits
__device__ float g_z[NB * OUTC * HW];          // 16 MB  z = W_out @ x
__device__ __nv_bfloat16 g_xh[NB * HW * CIN];  // 8 MB   x transposed [n][p][c], hi
__device__ __nv_bfloat16 g_xl[NB * HW * CIN];  // 8 MB   lo residual
__device__ __nv_bfloat16 g_wh[OUTC * CIN];     // W_out hi
__device__ __nv_bfloat16 g_wl[OUTC * CIN];     // W_out lo

__device__ __forceinline__ uint32_t smem_u32(const void* p) {
    uint32_t a;
    asm("{.reg .u64 t; cvta.to.shared.u64 t, %1; cvt.u32.u64 %0, t;}"
        : "=r"(a) : "l"(p));
    return a;
}

// ---------------------------------------------------------------------------
// Convert W_out to hi/lo bf16 (natural [m][c] layout)
// ---------------------------------------------------------------------------
__global__ void __launch_bounds__(256) convert_w_kernel(
        const float* __restrict__ W,
        __nv_bfloat16* __restrict__ wh, __nv_bfloat16* __restrict__ wl) {
    int idx = blockIdx.x * 256 + threadIdx.x;   // 65536 total
    float v = W[idx];
    __nv_bfloat16 h = __float2bfloat16(v);
    wh[idx] = h;
    wl[idx] = __float2bfloat16(v - __bfloat162float(h));
}

// ---------------------------------------------------------------------------
// Convert + transpose x: [n][c][p] fp32 -> [n][p][c] bf16 hi/lo (64x64 tiles)
// ---------------------------------------------------------------------------
__global__ void __launch_bounds__(256) convert_x_kernel(
        const float* __restrict__ X,
        __nv_bfloat16* __restrict__ xh, __nv_bfloat16* __restrict__ xl) {
    __shared__ float st[64][65];
    const int tid = threadIdx.x;
    const int pt = blockIdx.x * 64, ct = blockIdx.y * 64, n = blockIdx.z;
#pragma unroll
    for (int i = 0; i < 16; i++) {
        int linear = tid + i * 256;
        int p = linear & 63, c = linear >> 6;
        st[c][p] = X[((size_t)(n * CIN + ct + c)) * HW + pt + p];
    }
    __syncthreads();
    int p = tid >> 2, cs = (tid & 3) * 16;
    size_t ob = ((size_t)(n * HW + pt + p)) * CIN + ct + cs;
#pragma unroll
    for (int k = 0; k < 16; k++) {
        float v = st[cs + k][p];
        __nv_bfloat16 h = __float2bfloat16(v);
        xh[ob + k] = h;
        xl[ob + k] = __float2bfloat16(v - __bfloat162float(h));
    }
}

// ---------------------------------------------------------------------------
// z = W_out @ x via mma.sync bf16 (HMMA; tcgen05 is rejected by the harness's
// compute_103 PTX target).  2-term split: z = Whi@xhi + Whi@xlo + Wlo@xhi.
// Block = 128m x 128p, 8 warps (4m x 2p), warp = 32m x 64p.
// Both operands K-major -> mma row.col with plain (non-trans) ldmatrix.
// ---------------------------------------------------------------------------
#define STRZ 136   // bf16 elements per smem row (16B-aligned, conflict-free)

#define LDM_X4(r0, r1, r2, r3, addr) \
    asm volatile("ldmatrix.sync.aligned.m8n8.x4.shared.b16 {%0,%1,%2,%3}, [%4];" \
        : "=r"(r0), "=r"(r1), "=r"(r2), "=r"(r3) : "r"(addr))

#define MMA_BF16(d, a, b0v, b1v) \
    asm volatile("mma.sync.aligned.m16n8k16.row.col.f32.bf16.bf16.f32 " \
        "{%0,%1,%2,%3},{%4,%5,%6,%7},{%8,%9},{%0,%1,%2,%3};" \
        : "+f"((d)[0]), "+f"((d)[1]), "+f"((d)[2]), "+f"((d)[3]) \
        : "r"((a)[0]), "r"((a)[1]), "r"((a)[2]), "r"((a)[3]), \
          "r"(b0v), "r"(b1v))

__global__ void __launch_bounds__(256) zgemm_mma(
        const __nv_bfloat16* __restrict__ wh, const __nv_bfloat16* __restrict__ wl,
        const __nv_bfloat16* __restrict__ xh, const __nv_bfloat16* __restrict__ xl,
        float* __restrict__ Zo) {
    extern __shared__ __nv_bfloat16 sm[];
    __nv_bfloat16* sA = sm;                 // [128][STRZ]  W tile
    __nv_bfloat16* sB = sm + 128 * STRZ;    // [128][STRZ]  x^T tile

    const int tid = threadIdx.x, wid = tid >> 5, lane = tid & 31;
    const int p0 = blockIdx.x * 128, m0 = blockIdx.y * 128, n = blockIdx.z;
    const int warp_m = wid >> 1, warp_p = wid & 1;

    float acc[2][8][4];
#pragma unroll
    for (int mi = 0; mi < 2; mi++)
#pragma unroll
        for (int nf = 0; nf < 8; nf++)
#pragma unroll
            for (int q = 0; q < 4; q++) acc[mi][nf][q] = 0.0f;

    // per-lane ldmatrix row/col components (element units)
    const int aRow = warp_m * 32 + (lane & 15);
    const int aCol = (lane >> 4) << 3;
    const int bRow = warp_p * 64 + ((lane >> 4) << 3) + (lane & 7);
    const int bCol = ((lane >> 3) & 1) << 3;
    const uint32_t aBase = smem_u32(sA) + (uint32_t)(aRow * STRZ + aCol) * 2;
    const uint32_t bBase = smem_u32(sB) + (uint32_t)(bRow * STRZ + bCol) * 2;

    const int srow = tid >> 4, sseg = tid & 15;   // staging roles

    for (int kc = 0; kc < 6; kc++) {
        const __nv_bfloat16* A = (kc < 4) ? wh : wl;
        const __nv_bfloat16* B = (kc < 2 || kc >= 4) ? xh : xl;
        const int c0 = (kc & 1) * 128;

        __syncthreads();
#pragma unroll
        for (int i = 0; i < 8; i++) {
            int row = srow + i * 16;
            *(uint4*)(sA + row * STRZ + sseg * 8) =
                *(const uint4*)(A + (m0 + row) * CIN + c0 + sseg * 8);
            *(uint4*)(sB + row * STRZ + sseg * 8) =
                *(const uint4*)(B + ((size_t)(n * HW) + p0 + row) * CIN + c0 + sseg * 8);
        }
        __syncthreads();

#pragma unroll
        for (int ks = 0; ks < 8; ks++) {
            uint32_t a0[4], a1[4];
            LDM_X4(a0[0], a0[1], a0[2], a0[3], aBase + (ks * 16) * 2);
            LDM_X4(a1[0], a1[1], a1[2], a1[3],
                   aBase + (16 * STRZ + ks * 16) * 2);
            uint32_t b[4][4];
#pragma unroll
            for (int bi = 0; bi < 4; bi++)
                LDM_X4(b[bi][0], b[bi][1], b[bi][2], b[bi][3],
                       bBase + (bi * 16 * STRZ + ks * 16) * 2);
#pragma unroll
            for (int nf = 0; nf < 8; nf++) {
                int bi = nf >> 1, hp = (nf & 1) << 1;
                MMA_BF16(acc[0][nf], a0, b[bi][hp], b[bi][hp + 1]);
                MMA_BF16(acc[1][nf], a1, b[bi][hp], b[bi][hp + 1]);
            }
        }
    }

    // epilogue: c0,c1 -> (row, col..col+1); c2,c3 -> (row+8, ...)
    const int er = lane >> 2, ec = (lane & 3) * 2;
#pragma unroll
    for (int mi = 0; mi < 2; mi++) {
        const int mb = m0 + warp_m * 32 + mi * 16 + er;
#pragma unroll
        for (int nf = 0; nf < 8; nf++) {
            const int pcol = p0 + warp_p * 64 + nf * 8 + ec;
            float* z0 = Zo + ((size_t)(n * OUTC + mb)) * HW + pcol;
            *(float2*)z0 = make_float2(acc[mi][nf][0], acc[mi][nf][1]);
            *(float2*)(z0 + 8 * HW) = make_float2(acc[mi][nf][2], acc[mi][nf][3]);
        }
    }
}

// ---------------------------------------------------------------------------
// 1x1 down conv as GEMM (proven R5-measured FFMA2 version)
// ---------------------------------------------------------------------------
template<int MTILE>
__global__ void __launch_bounds__(256) gemm1x1_v(
        const float* __restrict__ X, const float* __restrict__ Wm,
        const float* __restrict__ bias, float* __restrict__ out,
        int C, int M) {
    __shared__ float sWt[256 * MTILE];   // [C][MTILE]
    const int m0 = blockIdx.y * MTILE;
    for (int idx = threadIdx.x; idx < C * MTILE; idx += 256)
        sWt[idx] = Wm[(m0 + (idx % MTILE)) * C + (idx / MTILE)];
    __syncthreads();

    const int p0  = (blockIdx.x * 256 + threadIdx.x) * 4;
    const int n   = p0 >> 12;
    const int pix = p0 & 4095;
    const float4* xb = (const float4*)(X + (size_t)n * C * HW) + (pix >> 2);

    u64 acc2[MTILE / 2][4];
#pragma unroll
    for (int mp = 0; mp < MTILE / 2; mp++) {
        float b0 = bias ? bias[m0 + 2 * mp]     : 0.0f;
        float b1 = bias ? bias[m0 + 2 * mp + 1] : 0.0f;
        u64 bp = pack2(b0, b1);
#pragma unroll
        for (int p = 0; p < 4; p++) acc2[mp][p] = bp;
    }

    const ulonglong2* sW2 = (const ulonglong2*)sWt;
#pragma unroll 4
    for (int c = 0; c < C; c++) {
        float4 xv = xb[c * (HW / 4)];
        u64 sx0 = splat2(xv.x), sx1 = splat2(xv.y);
        u64 sx2 = splat2(xv.z), sx3 = splat2(xv.w);
#pragma unroll
        for (int j = 0; j < MTILE / 4; j++) {
            ulonglong2 wv = sW2[c * (MTILE / 4) + j];
            fma2(acc2[2*j][0], sx0, wv.x);
            fma2(acc2[2*j][1], sx1, wv.x);
            fma2(acc2[2*j][2], sx2, wv.x);
            fma2(acc2[2*j][3], sx3, wv.x);
            fma2(acc2[2*j+1][0], sx0, wv.y);
            fma2(acc2[2*j+1][1], sx1, wv.y);
            fma2(acc2[2*j+1][2], sx2, wv.y);
            fma2(acc2[2*j+1][3], sx3, wv.y);
        }
    }

    float4* ob = (float4*)(out + (size_t)n * M * HW) + (pix >> 2);
#pragma unroll
    for (int mp = 0; mp < MTILE / 2; mp++) {
        float2 q0 = unpack2(acc2[mp][0]), q1 = unpack2(acc2[mp][1]);
        float2 q2 = unpack2(acc2[mp][2]), q3 = unpack2(acc2[mp][3]);
        ob[(m0 + 2 * mp    ) * (HW / 4)] = make_float4(q0.x, q1.x, q2.x, q3.x);
        ob[(m0 + 2 * mp + 1) * (HW / 4)] = make_float4(q0.y, q1.y, q2.y, q3.y);
    }
}

// ---------------------------------------------------------------------------
// 3x3 encoder conv (proven R5-measured FFMA2 version)
// ---------------------------------------------------------------------------
#define QC  20
#define ICC 8

__global__ void __launch_bounds__(256) enc_conv_kernel(
        const float* __restrict__ T, const float* __restrict__ Wenc,
        const float* __restrict__ benc, float* __restrict__ E) {
    __shared__ float sT[ICC * 18 * 34];
    __shared__ float sW[ICC * 9 * QC];

    const int wtile = blockIdx.x;
    const int n     = blockIdx.y >> 2;
    const int htile = blockIdx.y & 3;
    const int ch0   = blockIdx.z * QC;
    const int tid   = threadIdx.x;
    const int ty    = tid >> 5, tx = tid & 31;
    const int h0 = htile * 16 - 1, w0 = wtile * 32 - 1;

    u64 acc_t[QC / 2], acc_u[QC / 2];
#pragma unroll
    for (int qp = 0; qp < QC / 2; qp++) {
        u64 bp = pack2(benc[ch0 + 2 * qp], benc[ch0 + 2 * qp + 1]);
        acc_t[qp] = bp; acc_u[qp] = bp;
    }

    for (int icc = 0; icc < CM / ICC; icc++) {
        const int ic0 = icc * ICC;
        __syncthreads();
        for (int idx = tid; idx < ICC * 18 * 34; idx += 256) {
            int ch = idx / 612, rem = idx % 612;
            int r = rem / 34, col = rem % 34;
            int gr = h0 + r, gc = w0 + col;
            float v = 0.0f;
            if ((unsigned)gr < HH && (unsigned)gc < WW)
                v = T[((n * CM + ic0 + ch) * HH + gr) * WW + gc];
            sT[idx] = v;
        }
        for (int idx = tid; idx < ICC * 9 * QC; idx += 256) {
            int m = idx / (9 * QC), rem = idx % (9 * QC);
            int tap = rem / QC, q = rem % QC;
            sW[idx] = Wenc[((ch0 + q) * CM + ic0 + m) * 9 + tap];
        }
        __syncthreads();

        for (int m = 0; m < ICC; m++) {
            const float* tb = sT + m * 612 + ty * 34 + tx;
            const float* ub = tb + 8 * 34;
#pragma unroll
            for (int ki = 0; ki < 3; ki++) {
#pragma unroll
                for (int kj = 0; kj < 3; kj++) {
                    const int tap = ki * 3 + kj;
                    u64 at = splat2(tb[ki * 34 + kj]);
                    u64 au = splat2(ub[ki * 34 + kj]);
                    const ulonglong2* wb =
                        (const ulonglong2*)(sW + (m * 9 + tap) * QC);
#pragma unroll
                    for (int g = 0; g < QC / 4; g++) {
                        ulonglong2 wv = wb[g];
                        fma2(acc_t[2 * g],     at, wv.x);
                        fma2(acc_t[2 * g + 1], at, wv.y);
                        fma2(acc_u[2 * g],     au, wv.x);
                        fma2(acc_u[2 * g + 1], au, wv.y);
                    }
                }
            }
        }
    }

    const int h = htile * 16 + ty, w = wtile * 32 + tx;
#pragma unroll
    for (int qp = 0; qp < QC / 2; qp++) {
        float2 vt = unpack2(acc_t[qp]);
        float2 vu = unpack2(acc_u[qp]);
        E[((n * EOUT + ch0 + 2*qp    ) * HH + h    ) * WW + w] = vt.x;
        E[((n * EOUT + ch0 + 2*qp + 1) * HH + h    ) * WW + w] = vt.y;
        E[((n * EOUT + ch0 + 2*qp    ) * HH + h + 8) * WW + w] = vu.x;
        E[((n * EOUT + ch0 + 2*qp + 1) * HH + h + 8) * WW + w] = vu.y;
    }
}

// ---------------------------------------------------------------------------
// Fused softmax + reassembly + pixel-shuffle + bias (proven R8 version)
// ---------------------------------------------------------------------------
__global__ void __launch_bounds__(256) carafe_kernel(
        const float* __restrict__ E, const float* __restrict__ Z,
        const float* __restrict__ bout, float* __restrict__ out) {
    __shared__ float sZ[2][4 * 5 * 72];

    const int nh = blockIdx.x;
    const int n  = nh >> 6;
    const int h  = nh & 63;
    const int cquart = blockIdx.y;
    const int tid   = threadIdx.x;
    const int w     = tid & 63;
    const int psel  = (tid >> 6) & 1;
    const int cslot = tid >> 7;

    const int p0 = 2 * psel;
    float kr[50];
    const float* eb = E + (size_t)n * EOUT * HW + h * WW + w;
#pragma unroll
    for (int k = 0; k < 25; k++) {
        kr[k * 2 + 0] = eb[(k * 4 + p0 + 0) * HW];
        kr[k * 2 + 1] = eb[(k * 4 + p0 + 1) * HW];
    }
#pragma unroll
    for (int pp = 0; pp < 2; pp++) {
        float mx = kr[pp];
#pragma unroll
        for (int k = 1; k < 25; k++) mx = fmaxf(mx, kr[k * 2 + pp]);
        float s = 0.0f;
#pragma unroll
        for (int k = 0; k < 25; k++) {
            float ex = __expf(kr[k * 2 + pp] - mx);
            kr[k * 2 + pp] = ex;
            s += ex;
        }
        float inv = 1.0f / s;
#pragma unroll
        for (int k = 0; k < 25; k++) kr[k * 2 + pp] *= inv;
    }

    const int lane64 = tid & 63;
    const int sch    = tid >> 6;
    const int hch    = tid >> 5;
    const int t2     = tid & 31;
    float2* op = (float2*)out;

    auto stage = [&](int it, int buf) {
        const int cbase = cquart * 64 + it * 4;
        float4* sZ4 = (float4*)sZ[buf];
        const float4* zc = (const float4*)(Z +
            ((size_t)(n * OUTC + cbase + sch) * HH) * WW);
        int r = lane64 >> 4, g = lane64 & 15;
        int row = h - 2 + r;
        float4 v = make_float4(0.f, 0.f, 0.f, 0.f);
        if ((unsigned)row < HH) v = zc[row * 16 + g];
        sZ4[sch * 90 + r * 18 + 1 + g] = v;
        if (lane64 < 16) {
            int row2 = h + 2;
            float4 v2 = make_float4(0.f, 0.f, 0.f, 0.f);
            if ((unsigned)row2 < HH) v2 = zc[row2 * 16 + lane64];
            sZ4[sch * 90 + 4 * 18 + 1 + lane64] = v2;
        }
        if (tid < 128 && t2 < 20) {
            int rr = t2 >> 2, cc = t2 & 3;
            int hrow = h - 2 + rr;
            int wc = (cc < 2) ? cc - 2 : 62 + cc;
            float hv = 0.0f;
            if ((unsigned)hrow < HH && (unsigned)wc < WW)
                hv = Z[((size_t)(n * OUTC + cbase + hch) * HH + hrow) * WW + wc];
            sZ[buf][hch * 360 + rr * 72 + ((cc < 2) ? cc + 2 : 66 + cc)] = hv;
        }
    };

    stage(0, 0);
    __syncthreads();

    for (int it = 0; it < 16; it++) {
        if (it < 15) stage(it + 1, (it + 1) & 1);

        const int cbase = cquart * 64 + it * 4;
        const int c0 = cbase + 2 * cslot;
        const float* zb = sZ[it & 1] + (2 * cslot) * 360 + (w + 2);
        float a00 = 0.f, a01 = 0.f, a10 = 0.f, a11 = 0.f;
#pragma unroll
        for (int ki = 0; ki < 5; ki++) {
#pragma unroll
            for (int kj = 0; kj < 5; kj++) {
                int kk = ki * 5 + kj;
                float z0 = zb[ki * 72 + kj];
                float z1 = zb[360 + ki * 72 + kj];
                a00 += z0 * kr[kk * 2 + 0];
                a01 += z0 * kr[kk * 2 + 1];
                a10 += z1 * kr[kk * 2 + 0];
                a11 += z1 * kr[kk * 2 + 1];
            }
        }
        float b0 = __ldg(bout + c0), b1 = __ldg(bout + c0 + 1);
        int row = 2 * h + psel;
        op[((n * OUTC + c0    ) * 128 + row) * 64 + w] = make_float2(a00 + b0, a01 + b0);
        op[((n * OUTC + c0 + 1) * 128 + row) * 64 + w] = make_float2(a10 + b1, a11 + b1);
        __syncthreads();
    }
}

// ---------------------------------------------------------------------------
extern "C" void kernel_launch(void* const* d_in, const int* in_sizes, int n_in,
                              void* d_out, int out_size) {
    const float* x  = (const float*)d_in[0];
    const float* Wd = (const float*)d_in[1];
    const float* bd = (const float*)d_in[2];
    const float* We = (const float*)d_in[3];
    const float* be = (const float*)d_in[4];
    const float* Wo = (const float*)d_in[5];
    const float* bo = (const float*)d_in[6];
    float* out = (float*)d_out;

    static float* gt = nullptr;
    static float* ge = nullptr;
    static float* gz = nullptr;
    static __nv_bfloat16 *gxh, *gxl, *gwh, *gwl;
    static cudaStream_t s2;
    static cudaEvent_t ev_fork, ev_join;
    const int zg_smem = 2 * 128 * STRZ * 2;   // 69632 bytes
    if (!gt) {
        cudaGetSymbolAddress((void**)&gt,  g_t);
        cudaGetSymbolAddress((void**)&ge,  g_e);
        cudaGetSymbolAddress((void**)&gz,  g_z);
        cudaGetSymbolAddress((void**)&gxh, g_xh);
        cudaGetSymbolAddress((void**)&gxl, g_xl);
        cudaGetSymbolAddress((void**)&gwh, g_wh);
        cudaGetSymbolAddress((void**)&gwl, g_wl);
        cudaStreamCreateWithFlags(&s2, cudaStreamNonBlocking);
        cudaEventCreateWithFlags(&ev_fork, cudaEventDisableTiming);
        cudaEventCreateWithFlags(&ev_join, cudaEventDisableTiming);
        cudaFuncSetAttribute(zgemm_mma,
                             cudaFuncAttributeMaxDynamicSharedMemorySize, zg_smem);
    }

    // Fork: z path (convert + tensor-core GEMM) overlaps the fp32 t/e path.
    cudaEventRecord(ev_fork, 0);
    cudaStreamWaitEvent(s2, ev_fork, 0);
    convert_w_kernel<<<256, 256, 0, s2>>>(Wo, gwh, gwl);
    convert_x_kernel<<<dim3(64, 4, 4), 256, 0, s2>>>(x, gxh, gxl);
    zgemm_mma<<<dim3(32, 2, 4), 256, zg_smem, s2>>>(gwh, gwl, gxh, gxl, gz);
    cudaEventRecord(ev_join, s2);

    // Main path: t = W_down @ x + b ; e = conv3x3(t) + b
    gemm1x1_v<8><<<dim3(16, 8), 256>>>(x, Wd, bd, gt, CIN, CM);
    enc_conv_kernel<<<dim3(2, 16, 5), 256>>>(gt, We, be, ge);

    // Join, then fused reassembly.
    cudaStreamWaitEvent(0, ev_join, 0);
    carafe_kernel<<<dim3(256, 4), 256>>>(ge, gz, bo, out);
}

// round 14
// speedup vs baseline: 1.5479x; 1.5479x over previous
#include <cuda_runtime.h>
#include <cuda_bf16.h>
#include <math.h>
#include <stdint.h>

// Shapes (fixed by the problem)
#define NB   4
#define CIN  256
#define HH   64
#define WW   64
#define HW   4096
#define CM   64
#define EOUT 100
#define OUTC 256

typedef unsigned long long u64;

// ---- packed fp32x2 helpers (Blackwell FFMA2 via PTX) ----------------------
__device__ __forceinline__ u64 pack2(float lo, float hi) {
    u64 d; asm("mov.b64 %0,{%1,%2};" : "=l"(d) : "f"(lo), "f"(hi)); return d;
}
__device__ __forceinline__ u64 splat2(float v) {
    u64 d; asm("mov.b64 %0,{%1,%1};" : "=l"(d) : "f"(v)); return d;
}
__device__ __forceinline__ void fma2(u64& acc, u64 a, u64 b) {
    asm("fma.rn.f32x2 %0,%1,%2,%0;" : "+l"(acc) : "l"(a), "l"(b));
}
__device__ __forceinline__ float2 unpack2(u64 d) {
    float2 r; asm("mov.b64 {%0,%1},%2;" : "=f"(r.x), "=f"(r.y) : "l"(d)); return r;
}

// Scratch (device globals; allocation is forbidden)
__device__ float g_t[NB * CM * HW];            // 4 MB   down-conv output
__device__ float g_e[NB * EOUT * HW];          // 6.5 MB encoder logits
__device__ float g_z[NB * OUTC * HW];          // 16 MB  z = W_out @ x
__device__ __nv_bfloat16 g_xh[NB * HW * CIN];  // 8 MB   x transposed [n][p][c], hi
__device__ __nv_bfloat16 g_xl[NB * HW * CIN];  // 8 MB   lo residual
__device__ __nv_bfloat16 g_wh[OUTC * CIN];     // W_out hi
__device__ __nv_bfloat16 g_wl[OUTC * CIN];     // W_out lo
__device__ __nv_bfloat16 g_wdh[CM * CIN];      // W_down hi
__device__ __nv_bfloat16 g_wdl[CM * CIN];      // W_down lo

__device__ __forceinline__ uint32_t smem_u32(const void* p) {
    uint32_t a;
    asm("{.reg .u64 t; cvta.to.shared.u64 t, %1; cvt.u32.u64 %0, t;}"
        : "=r"(a) : "l"(p));
    return a;
}

// ---------------------------------------------------------------------------
// Convert a weight matrix to hi/lo bf16 (natural [m][c] layout)
// ---------------------------------------------------------------------------
__global__ void __launch_bounds__(256) convert_w_kernel(
        const float* __restrict__ W,
        __nv_bfloat16* __restrict__ wh, __nv_bfloat16* __restrict__ wl) {
    int idx = blockIdx.x * 256 + threadIdx.x;
    float v = W[idx];
    __nv_bfloat16 h = __float2bfloat16(v);
    wh[idx] = h;
    wl[idx] = __float2bfloat16(v - __bfloat162float(h));
}

// ---------------------------------------------------------------------------
// Convert + transpose x: [n][c][p] fp32 -> [n][p][c] bf16 hi/lo (64x64 tiles)
// ---------------------------------------------------------------------------
__global__ void __launch_bounds__(256) convert_x_kernel(
        const float* __restrict__ X,
        __nv_bfloat16* __restrict__ xh, __nv_bfloat16* __restrict__ xl) {
    __shared__ float st[64][65];
    const int tid = threadIdx.x;
    const int pt = blockIdx.x * 64, ct = blockIdx.y * 64, n = blockIdx.z;
#pragma unroll
    for (int i = 0; i < 16; i++) {
        int linear = tid + i * 256;
        int p = linear & 63, c = linear >> 6;
        st[c][p] = X[((size_t)(n * CIN + ct + c)) * HW + pt + p];
    }
    __syncthreads();
    int p = tid >> 2, cs = (tid & 3) * 16;
    size_t ob = ((size_t)(n * HW + pt + p)) * CIN + ct + cs;
#pragma unroll
    for (int k = 0; k < 16; k++) {
        float v = st[cs + k][p];
        __nv_bfloat16 h = __float2bfloat16(v);
        xh[ob + k] = h;
        xl[ob + k] = __float2bfloat16(v - __bfloat162float(h));
    }
}

// ---------------------------------------------------------------------------
// Generic bf16 split GEMM on mma.sync (fragment layout VERIFIED in R11,
// rel_err 4.7e-6):  out[n][m][p] (+bias) = Ahi@Bhi + Ahi@Blo + Alo@Bhi.
// Block tile: (WM*32) m  x  (WP*NF*8) p;  8 warps = WM x WP; warp = 32m x NF*8p.
//   z:  WM=4, WP=2, NF=8  -> 128m x 128p, grid (32, 2, 4)
//   t:  WM=2, WP=4, NF=4  ->  64m x 128p, grid (32, 1, 4)
// Both operands K-major -> mma row.col with plain ldmatrix.
// ---------------------------------------------------------------------------
#define STRZ 136   // bf16 elements per smem row (16B-aligned, conflict-free)

#define LDM_X4(r0, r1, r2, r3, addr) \
    asm volatile("ldmatrix.sync.aligned.m8n8.x4.shared.b16 {%0,%1,%2,%3}, [%4];" \
        : "=r"(r0), "=r"(r1), "=r"(r2), "=r"(r3) : "r"(addr))

#define MMA_BF16(d, a, b0v, b1v) \
    asm volatile("mma.sync.aligned.m16n8k16.row.col.f32.bf16.bf16.f32 " \
        "{%0,%1,%2,%3},{%4,%5,%6,%7},{%8,%9},{%0,%1,%2,%3};" \
        : "+f"((d)[0]), "+f"((d)[1]), "+f"((d)[2]), "+f"((d)[3]) \
        : "r"((a)[0]), "r"((a)[1]), "r"((a)[2]), "r"((a)[3]), \
          "r"(b0v), "r"(b1v))

template<int WM, int WP, int NF>
__global__ void __launch_bounds__(256) gemm_mma(
        const __nv_bfloat16* __restrict__ ah, const __nv_bfloat16* __restrict__ al,
        const __nv_bfloat16* __restrict__ bh, const __nv_bfloat16* __restrict__ bl,
        float* __restrict__ Out, int M, const float* __restrict__ bias) {
    constexpr int AR = WM * 32;        // A rows per block
    constexpr int BR = WP * NF * 8;    // B rows (p) per block
    extern __shared__ __nv_bfloat16 sm[];
    __nv_bfloat16* sA = sm;              // [AR][STRZ]
    __nv_bfloat16* sB = sm + AR * STRZ;  // [BR][STRZ]

    const int tid = threadIdx.x, wid = tid >> 5, lane = tid & 31;
    const int p0 = blockIdx.x * BR, m0 = blockIdx.y * AR, n = blockIdx.z;
    const int warp_m = wid / WP, warp_p = wid % WP;

    float acc[2][NF][4];
#pragma unroll
    for (int mi = 0; mi < 2; mi++)
#pragma unroll
        for (int nf = 0; nf < NF; nf++)
#pragma unroll
            for (int q = 0; q < 4; q++) acc[mi][nf][q] = 0.0f;

    const int aRow = warp_m * 32 + (lane & 15);
    const int aCol = (lane >> 4) << 3;
    const int bRow = warp_p * (NF * 8) + ((lane >> 4) << 3) + (lane & 7);
    const int bCol = ((lane >> 3) & 1) << 3;
    const uint32_t aBase = smem_u32(sA) + (uint32_t)(aRow * STRZ + aCol) * 2;
    const uint32_t bBase = smem_u32(sB) + (uint32_t)(bRow * STRZ + bCol) * 2;

    for (int kc = 0; kc < 6; kc++) {
        const __nv_bfloat16* A = (kc < 4) ? ah : al;
        const __nv_bfloat16* B = (kc < 2 || kc >= 4) ? bh : bl;
        const int c0 = (kc & 1) * 128;

        __syncthreads();
#pragma unroll
        for (int idx = tid; idx < AR * 16; idx += 256) {
            int row = idx >> 4, seg = idx & 15;
            *(uint4*)(sA + row * STRZ + seg * 8) =
                *(const uint4*)(A + (m0 + row) * CIN + c0 + seg * 8);
        }
#pragma unroll
        for (int idx = tid; idx < BR * 16; idx += 256) {
            int row = idx >> 4, seg = idx & 15;
            *(uint4*)(sB + row * STRZ + seg * 8) =
                *(const uint4*)(B + ((size_t)(n * HW) + p0 + row) * CIN + c0 + seg * 8);
        }
        __syncthreads();

#pragma unroll
        for (int ks = 0; ks < 8; ks++) {
            uint32_t a0[4], a1[4];
            LDM_X4(a0[0], a0[1], a0[2], a0[3], aBase + (ks * 16) * 2);
            LDM_X4(a1[0], a1[1], a1[2], a1[3], aBase + (16 * STRZ + ks * 16) * 2);
            uint32_t b[NF / 2][4];
#pragma unroll
            for (int bi = 0; bi < NF / 2; bi++)
                LDM_X4(b[bi][0], b[bi][1], b[bi][2], b[bi][3],
                       bBase + (bi * 16 * STRZ + ks * 16) * 2);
#pragma unroll
            for (int nf = 0; nf < NF; nf++) {
                int bi = nf >> 1, hp = (nf & 1) << 1;
                MMA_BF16(acc[0][nf], a0, b[bi][hp], b[bi][hp + 1]);
                MMA_BF16(acc[1][nf], a1, b[bi][hp], b[bi][hp + 1]);
            }
        }
    }

    // epilogue: c0,c1 -> (row, col..col+1); c2,c3 -> (row+8, ...)
    const int er = lane >> 2, ec = (lane & 3) * 2;
#pragma unroll
    for (int mi = 0; mi < 2; mi++) {
        const int mb = m0 + warp_m * 32 + mi * 16 + er;
        const float bv0 = bias ? bias[mb]     : 0.0f;
        const float bv1 = bias ? bias[mb + 8] : 0.0f;
#pragma unroll
        for (int nf = 0; nf < NF; nf++) {
            const int pcol = p0 + warp_p * (NF * 8) + nf * 8 + ec;
            float* z0 = Out + ((size_t)(n * M + mb)) * HW + pcol;
            *(float2*)z0 = make_float2(acc[mi][nf][0] + bv0, acc[mi][nf][1] + bv0);
            *(float2*)(z0 + 8 * HW) =
                make_float2(acc[mi][nf][2] + bv1, acc[mi][nf][3] + bv1);
        }
    }
}

// ---------------------------------------------------------------------------
// 3x3 encoder conv (proven R5-measured FFMA2 version)
// ---------------------------------------------------------------------------
#define QC  20
#define ICC 8

__global__ void __launch_bounds__(256) enc_conv_kernel(
        const float* __restrict__ T, const float* __restrict__ Wenc,
        const float* __restrict__ benc, float* __restrict__ E) {
    __shared__ float sT[ICC * 18 * 34];
    __shared__ float sW[ICC * 9 * QC];

    const int wtile = blockIdx.x;
    const int n     = blockIdx.y >> 2;
    const int htile = blockIdx.y & 3;
    const int ch0   = blockIdx.z * QC;
    const int tid   = threadIdx.x;
    const int ty    = tid >> 5, tx = tid & 31;
    const int h0 = htile * 16 - 1, w0 = wtile * 32 - 1;

    u64 acc_t[QC / 2], acc_u[QC / 2];
#pragma unroll
    for (int qp = 0; qp < QC / 2; qp++) {
        u64 bp = pack2(benc[ch0 + 2 * qp], benc[ch0 + 2 * qp + 1]);
        acc_t[qp] = bp; acc_u[qp] = bp;
    }

    for (int icc = 0; icc < CM / ICC; icc++) {
        const int ic0 = icc * ICC;
        __syncthreads();
        for (int idx = tid; idx < ICC * 18 * 34; idx += 256) {
            int ch = idx / 612, rem = idx % 612;
            int r = rem / 34, col = rem % 34;
            int gr = h0 + r, gc = w0 + col;
            float v = 0.0f;
            if ((unsigned)gr < HH && (unsigned)gc < WW)
                v = T[((n * CM + ic0 + ch) * HH + gr) * WW + gc];
            sT[idx] = v;
        }
        for (int idx = tid; idx < ICC * 9 * QC; idx += 256) {
            int m = idx / (9 * QC), rem = idx % (9 * QC);
            int tap = rem / QC, q = rem % QC;
            sW[idx] = Wenc[((ch0 + q) * CM + ic0 + m) * 9 + tap];
        }
        __syncthreads();

        for (int m = 0; m < ICC; m++) {
            const float* tb = sT + m * 612 + ty * 34 + tx;
            const float* ub = tb + 8 * 34;
#pragma unroll
            for (int ki = 0; ki < 3; ki++) {
#pragma unroll
                for (int kj = 0; kj < 3; kj++) {
                    const int tap = ki * 3 + kj;
                    u64 at = splat2(tb[ki * 34 + kj]);
                    u64 au = splat2(ub[ki * 34 + kj]);
                    const ulonglong2* wb =
                        (const ulonglong2*)(sW + (m * 9 + tap) * QC);
#pragma unroll
                    for (int g = 0; g < QC / 4; g++) {
                        ulonglong2 wv = wb[g];
                        fma2(acc_t[2 * g],     at, wv.x);
                        fma2(acc_t[2 * g + 1], at, wv.y);
                        fma2(acc_u[2 * g],     au, wv.x);
                        fma2(acc_u[2 * g + 1], au, wv.y);
                    }
                }
            }
        }
    }

    const int h = htile * 16 + ty, w = wtile * 32 + tx;
#pragma unroll
    for (int qp = 0; qp < QC / 2; qp++) {
        float2 vt = unpack2(acc_t[qp]);
        float2 vu = unpack2(acc_u[qp]);
        E[((n * EOUT + ch0 + 2*qp    ) * HH + h    ) * WW + w] = vt.x;
        E[((n * EOUT + ch0 + 2*qp + 1) * HH + h    ) * WW + w] = vt.y;
        E[((n * EOUT + ch0 + 2*qp    ) * HH + h + 8) * WW + w] = vu.x;
        E[((n * EOUT + ch0 + 2*qp + 1) * HH + h + 8) * WW + w] = vu.y;
    }
}

// ---------------------------------------------------------------------------
// Fused softmax + reassembly + pixel-shuffle + bias (proven R8 version)
// ---------------------------------------------------------------------------
__global__ void __launch_bounds__(256) carafe_kernel(
        const float* __restrict__ E, const float* __restrict__ Z,
        const float* __restrict__ bout, float* __restrict__ out) {
    __shared__ float sZ[2][4 * 5 * 72];

    const int nh = blockIdx.x;
    const int n  = nh >> 6;
    const int h  = nh & 63;
    const int cquart = blockIdx.y;
    const int tid   = threadIdx.x;
    const int w     = tid & 63;
    const int psel  = (tid >> 6) & 1;
    const int cslot = tid >> 7;

    const int p0 = 2 * psel;
    float kr[50];
    const float* eb = E + (size_t)n * EOUT * HW + h * WW + w;
#pragma unroll
    for (int k = 0; k < 25; k++) {
        kr[k * 2 + 0] = eb[(k * 4 + p0 + 0) * HW];
        kr[k * 2 + 1] = eb[(k * 4 + p0 + 1) * HW];
    }
#pragma unroll
    for (int pp = 0; pp < 2; pp++) {
        float mx = kr[pp];
#pragma unroll
        for (int k = 1; k < 25; k++) mx = fmaxf(mx, kr[k * 2 + pp]);
        float s = 0.0f;
#pragma unroll
        for (int k = 0; k < 25; k++) {
            float ex = __expf(kr[k * 2 + pp] - mx);
            kr[k * 2 + pp] = ex;
            s += ex;
        }
        float inv = 1.0f / s;
#pragma unroll
        for (int k = 0; k < 25; k++) kr[k * 2 + pp] *= inv;
    }

    const int lane64 = tid & 63;
    const int sch    = tid >> 6;
    const int hch    = tid >> 5;
    const int t2     = tid & 31;
    float2* op = (float2*)out;

    auto stage = [&](int it, int buf) {
        const int cbase = cquart * 64 + it * 4;
        float4* sZ4 = (float4*)sZ[buf];
        const float4* zc = (const float4*)(Z +
            ((size_t)(n * OUTC + cbase + sch) * HH) * WW);
        int r = lane64 >> 4, g = lane64 & 15;
        int row = h - 2 + r;
        float4 v = make_float4(0.f, 0.f, 0.f, 0.f);
        if ((unsigned)row < HH) v = zc[row * 16 + g];
        sZ4[sch * 90 + r * 18 + 1 + g] = v;
        if (lane64 < 16) {
            int row2 = h + 2;
            float4 v2 = make_float4(0.f, 0.f, 0.f, 0.f);
            if ((unsigned)row2 < HH) v2 = zc[row2 * 16 + lane64];
            sZ4[sch * 90 + 4 * 18 + 1 + lane64] = v2;
        }
        if (tid < 128 && t2 < 20) {
            int rr = t2 >> 2, cc = t2 & 3;
            int hrow = h - 2 + rr;
            int wc = (cc < 2) ? cc - 2 : 62 + cc;
            float hv = 0.0f;
            if ((unsigned)hrow < HH && (unsigned)wc < WW)
                hv = Z[((size_t)(n * OUTC + cbase + hch) * HH + hrow) * WW + wc];
            sZ[buf][hch * 360 + rr * 72 + ((cc < 2) ? cc + 2 : 66 + cc)] = hv;
        }
    };

    stage(0, 0);
    __syncthreads();

    for (int it = 0; it < 16; it++) {
        if (it < 15) stage(it + 1, (it + 1) & 1);

        const int cbase = cquart * 64 + it * 4;
        const int c0 = cbase + 2 * cslot;
        const float* zb = sZ[it & 1] + (2 * cslot) * 360 + (w + 2);
        float a00 = 0.f, a01 = 0.f, a10 = 0.f, a11 = 0.f;
#pragma unroll
        for (int ki = 0; ki < 5; ki++) {
#pragma unroll
            for (int kj = 0; kj < 5; kj++) {
                int kk = ki * 5 + kj;
                float z0 = zb[ki * 72 + kj];
                float z1 = zb[360 + ki * 72 + kj];
                a00 += z0 * kr[kk * 2 + 0];
                a01 += z0 * kr[kk * 2 + 1];
                a10 += z1 * kr[kk * 2 + 0];
                a11 += z1 * kr[kk * 2 + 1];
            }
        }
        float b0 = __ldg(bout + c0), b1 = __ldg(bout + c0 + 1);
        int row = 2 * h + psel;
        op[((n * OUTC + c0    ) * 128 + row) * 64 + w] = make_float2(a00 + b0, a01 + b0);
        op[((n * OUTC + c0 + 1) * 128 + row) * 64 + w] = make_float2(a10 + b1, a11 + b1);
        __syncthreads();
    }
}

// ---------------------------------------------------------------------------
extern "C" void kernel_launch(void* const* d_in, const int* in_sizes, int n_in,
                              void* d_out, int out_size) {
    const float* x  = (const float*)d_in[0];
    const float* Wd = (const float*)d_in[1];
    const float* bd = (const float*)d_in[2];
    const float* We = (const float*)d_in[3];
    const float* be = (const float*)d_in[4];
    const float* Wo = (const float*)d_in[5];
    const float* bo = (const float*)d_in[6];
    float* out = (float*)d_out;

    static float* gt = nullptr;
    static float* ge = nullptr;
    static float* gz = nullptr;
    static __nv_bfloat16 *gxh, *gxl, *gwh, *gwl, *gwdh, *gwdl;
    static cudaStream_t s2;
    static cudaEvent_t ev_fork, ev_join;
    const int z_smem = (128 + 128) * STRZ * 2;   // 69632 B
    const int t_smem = (64 + 128) * STRZ * 2;    // 52224 B
    if (!gt) {
        cudaGetSymbolAddress((void**)&gt,   g_t);
        cudaGetSymbolAddress((void**)&ge,   g_e);
        cudaGetSymbolAddress((void**)&gz,   g_z);
        cudaGetSymbolAddress((void**)&gxh,  g_xh);
        cudaGetSymbolAddress((void**)&gxl,  g_xl);
        cudaGetSymbolAddress((void**)&gwh,  g_wh);
        cudaGetSymbolAddress((void**)&gwl,  g_wl);
        cudaGetSymbolAddress((void**)&gwdh, g_wdh);
        cudaGetSymbolAddress((void**)&gwdl, g_wdl);
        cudaStreamCreateWithFlags(&s2, cudaStreamNonBlocking);
        cudaEventCreateWithFlags(&ev_fork, cudaEventDisableTiming);
        cudaEventCreateWithFlags(&ev_join, cudaEventDisableTiming);
        cudaFuncSetAttribute((const void*)gemm_mma<4, 2, 8>,
                             cudaFuncAttributeMaxDynamicSharedMemorySize, z_smem);
        cudaFuncSetAttribute((const void*)gemm_mma<2, 4, 4>,
                             cudaFuncAttributeMaxDynamicSharedMemorySize, t_smem);
    }

    // Converts (shared by both GEMMs)
    convert_w_kernel<<<256, 256>>>(Wo, gwh, gwl);   // 65536 elements
    convert_w_kernel<<<64, 256>>>(Wd, gwdh, gwdl);  // 16384 elements
    convert_x_kernel<<<dim3(64, 4, 4), 256>>>(x, gxh, gxl);

    // Fork: z = W_out @ x on tensor cores, concurrent with t/e path.
    cudaEventRecord(ev_fork, 0);
    cudaStreamWaitEvent(s2, ev_fork, 0);
    gemm_mma<4, 2, 8><<<dim3(32, 2, 4), 256, z_smem, s2>>>(
        gwh, gwl, gxh, gxl, gz, OUTC, nullptr);
    cudaEventRecord(ev_join, s2);

    // Main path: t = W_down @ x + b_down (tensor cores), then e = conv3x3(t)+b
    gemm_mma<2, 4, 4><<<dim3(32, 1, 4), 256, t_smem>>>(
        gwdh, gwdl, gxh, gxl, gt, CM, bd);
    enc_conv_kernel<<<dim3(2, 16, 5), 256>>>(gt, We, be, ge);

    // Join, then fused reassembly.
    cudaStreamWaitEvent(0, ev_join, 0);
    carafe_kernel<<<dim3(256, 4), 256>>>(ge, gz, bo, out);
}

// round 15
// speedup vs baseline: 1.7116x; 1.1058x over previous
#include <cuda_runtime.h>
#include <cuda_bf16.h>
#include <math.h>
#include <stdint.h>

// Shapes (fixed by the problem)
#define NB   4
#define CIN  256
#define HH   64
#define WW   64
#define HW   4096
#define CM   64
#define EOUT 100
#define OUTC 256

typedef unsigned long long u64;

// Scratch (device globals; allocation is forbidden)
__device__ float g_e[NB * EOUT * HW];           // 6.5 MB encoder logits
__device__ float g_z[NB * OUTC * HW];           // 16 MB  z = W_out @ x
__device__ __nv_bfloat16 g_xh[NB * HW * CIN];   // x^T [n][p][c] hi
__device__ __nv_bfloat16 g_xl[NB * HW * CIN];   // lo residual
__device__ __nv_bfloat16 g_wh[OUTC * CIN];      // W_out hi
__device__ __nv_bfloat16 g_wl[OUTC * CIN];      // W_out lo
__device__ __nv_bfloat16 g_wdh[CM * CIN];       // W_down hi
__device__ __nv_bfloat16 g_wdl[CM * CIN];       // W_down lo
__device__ __nv_bfloat16 g_th[NB * HW * CM];    // t^T [n][p][m] hi
__device__ __nv_bfloat16 g_tl[NB * HW * CM];    // t^T lo
__device__ __nv_bfloat16 g_weh[128 * 576];      // Wenc repacked [qpad][tap*64+m] hi
__device__ __nv_bfloat16 g_wel[128 * 576];      // lo

__device__ __forceinline__ uint32_t smem_u32(const void* p) {
    uint32_t a;
    asm("{.reg .u64 t; cvta.to.shared.u64 t, %1; cvt.u32.u64 %0, t;}"
        : "=r"(a) : "l"(p));
    return a;
}

// ---------------------------------------------------------------------------
// Converts
// ---------------------------------------------------------------------------
__global__ void __launch_bounds__(256) convert_w_kernel(
        const float* __restrict__ W,
        __nv_bfloat16* __restrict__ wh, __nv_bfloat16* __restrict__ wl) {
    int idx = blockIdx.x * 256 + threadIdx.x;
    float v = W[idx];
    __nv_bfloat16 h = __float2bfloat16(v);
    wh[idx] = h;
    wl[idx] = __float2bfloat16(v - __bfloat162float(h));
}

// Wenc [100][64][3][3] fp32 -> [128 pad][tap*64+m] bf16 hi/lo
__global__ void __launch_bounds__(256) convert_wenc_kernel(
        const float* __restrict__ W,
        __nv_bfloat16* __restrict__ wh, __nv_bfloat16* __restrict__ wl) {
    int idx = blockIdx.x * 256 + threadIdx.x;   // 128*576 = 73728
    if (idx >= 128 * 576) return;
    int q = idx / 576, k = idx % 576;
    int tap = k >> 6, m = k & 63;
    float v = (q < EOUT) ? W[(q * CM + m) * 9 + tap] : 0.0f;
    __nv_bfloat16 h = __float2bfloat16(v);
    wh[idx] = h;
    wl[idx] = __float2bfloat16(v - __bfloat162float(h));
}

// x: [n][c][p] fp32 -> [n][p][c] bf16 hi/lo (64x64 transpose tiles)
__global__ void __launch_bounds__(256) convert_x_kernel(
        const float* __restrict__ X,
        __nv_bfloat16* __restrict__ xh, __nv_bfloat16* __restrict__ xl) {
    __shared__ float st[64][65];
    const int tid = threadIdx.x;
    const int pt = blockIdx.x * 64, ct = blockIdx.y * 64, n = blockIdx.z;
#pragma unroll
    for (int i = 0; i < 16; i++) {
        int linear = tid + i * 256;
        int p = linear & 63, c = linear >> 6;
        st[c][p] = X[((size_t)(n * CIN + ct + c)) * HW + pt + p];
    }
    __syncthreads();
    int p = tid >> 2, cs = (tid & 3) * 16;
    size_t ob = ((size_t)(n * HW + pt + p)) * CIN + ct + cs;
#pragma unroll
    for (int k = 0; k < 16; k++) {
        float v = st[cs + k][p];
        __nv_bfloat16 h = __float2bfloat16(v);
        xh[ob + k] = h;
        xl[ob + k] = __float2bfloat16(v - __bfloat162float(h));
    }
}

// ---------------------------------------------------------------------------
// MMA primitives (fragment layout VERIFIED on HW in R11/R14, rel_err ~5e-6)
// ---------------------------------------------------------------------------
#define STRZ 136   // smem row stride (bf16) for z / tT tiles

#define LDM_X4(r0, r1, r2, r3, addr) \
    asm volatile("ldmatrix.sync.aligned.m8n8.x4.shared.b16 {%0,%1,%2,%3}, [%4];" \
        : "=r"(r0), "=r"(r1), "=r"(r2), "=r"(r3) : "r"(addr))

#define MMA_BF16(d, a, b0v, b1v) \
    asm volatile("mma.sync.aligned.m16n8k16.row.col.f32.bf16.bf16.f32 " \
        "{%0,%1,%2,%3},{%4,%5,%6,%7},{%8,%9},{%0,%1,%2,%3};" \
        : "+f"((d)[0]), "+f"((d)[1]), "+f"((d)[2]), "+f"((d)[3]) \
        : "r"((a)[0]), "r"((a)[1]), "r"((a)[2]), "r"((a)[3]), \
          "r"(b0v), "r"(b1v))

// ---------------------------------------------------------------------------
// z = W_out @ x  (unchanged from R14 — measured 27 us, tensor 38.7%)
// Block 128m x 128p; 8 warps 4x2; out fp32 [n][m][p].
// ---------------------------------------------------------------------------
__global__ void __launch_bounds__(256) zgemm_mma(
        const __nv_bfloat16* __restrict__ ah, const __nv_bfloat16* __restrict__ al,
        const __nv_bfloat16* __restrict__ bh, const __nv_bfloat16* __restrict__ bl,
        float* __restrict__ Out) {
    extern __shared__ __nv_bfloat16 sm[];
    __nv_bfloat16* sA = sm;                 // [128][STRZ]
    __nv_bfloat16* sB = sm + 128 * STRZ;    // [128][STRZ]

    const int tid = threadIdx.x, wid = tid >> 5, lane = tid & 31;
    const int p0 = blockIdx.x * 128, m0 = blockIdx.y * 128, n = blockIdx.z;
    const int warp_m = wid >> 1, warp_p = wid & 1;

    float acc[2][8][4];
#pragma unroll
    for (int mi = 0; mi < 2; mi++)
#pragma unroll
        for (int nf = 0; nf < 8; nf++)
#pragma unroll
            for (int q = 0; q < 4; q++) acc[mi][nf][q] = 0.0f;

    const int aRow = warp_m * 32 + (lane & 15);
    const int aCol = (lane >> 4) << 3;
    const int bRow = warp_p * 64 + ((lane >> 4) << 3) + (lane & 7);
    const int bCol = ((lane >> 3) & 1) << 3;
    const uint32_t aBase = smem_u32(sA) + (uint32_t)(aRow * STRZ + aCol) * 2;
    const uint32_t bBase = smem_u32(sB) + (uint32_t)(bRow * STRZ + bCol) * 2;

    for (int kc = 0; kc < 6; kc++) {
        const __nv_bfloat16* A = (kc < 4) ? ah : al;
        const __nv_bfloat16* B = (kc < 2 || kc >= 4) ? bh : bl;
        const int c0 = (kc & 1) * 128;

        __syncthreads();
        for (int idx = tid; idx < 128 * 16; idx += 256) {
            int row = idx >> 4, seg = idx & 15;
            *(uint4*)(sA + row * STRZ + seg * 8) =
                *(const uint4*)(A + (m0 + row) * CIN + c0 + seg * 8);
            *(uint4*)(sB + row * STRZ + seg * 8) =
                *(const uint4*)(B + ((size_t)(n * HW) + p0 + row) * CIN + c0 + seg * 8);
        }
        __syncthreads();

#pragma unroll
        for (int ks = 0; ks < 8; ks++) {
            uint32_t a0[4], a1[4];
            LDM_X4(a0[0], a0[1], a0[2], a0[3], aBase + (ks * 16) * 2);
            LDM_X4(a1[0], a1[1], a1[2], a1[3], aBase + (16 * STRZ + ks * 16) * 2);
            uint32_t b[4][4];
#pragma unroll
            for (int bi = 0; bi < 4; bi++)
                LDM_X4(b[bi][0], b[bi][1], b[bi][2], b[bi][3],
                       bBase + (bi * 16 * STRZ + ks * 16) * 2);
#pragma unroll
            for (int nf = 0; nf < 8; nf++) {
                int bi = nf >> 1, hp = (nf & 1) << 1;
                MMA_BF16(acc[0][nf], a0, b[bi][hp], b[bi][hp + 1]);
                MMA_BF16(acc[1][nf], a1, b[bi][hp], b[bi][hp + 1]);
            }
        }
    }

    const int er = lane >> 2, ec = (lane & 3) * 2;
#pragma unroll
    for (int mi = 0; mi < 2; mi++) {
        const int mb = m0 + warp_m * 32 + mi * 16 + er;
#pragma unroll
        for (int nf = 0; nf < 8; nf++) {
            const int pcol = p0 + warp_p * 64 + nf * 8 + ec;
            float* z0 = Out + ((size_t)(n * OUTC + mb)) * HW + pcol;
            *(float2*)z0 = make_float2(acc[mi][nf][0], acc[mi][nf][1]);
            *(float2*)(z0 + 8 * HW) = make_float2(acc[mi][nf][2], acc[mi][nf][3]);
        }
    }
}

// ---------------------------------------------------------------------------
// t^T = (W_down @ x)^T + b_down, output bf16 hi/lo [n][p][64].
// A = x^T (128 p rows), B = W_down (64 m rows).  8 warps 4x2, NF=4.
// ---------------------------------------------------------------------------
__global__ void __launch_bounds__(256) tgemmT_mma(
        const __nv_bfloat16* __restrict__ xh, const __nv_bfloat16* __restrict__ xl,
        const __nv_bfloat16* __restrict__ wdh, const __nv_bfloat16* __restrict__ wdl,
        const float* __restrict__ bias,
        __nv_bfloat16* __restrict__ th, __nv_bfloat16* __restrict__ tl) {
    extern __shared__ __nv_bfloat16 sm[];
    __nv_bfloat16* sA = sm;                 // [128][STRZ]  x^T
    __nv_bfloat16* sB = sm + 128 * STRZ;    // [64][STRZ]   W_down

    const int tid = threadIdx.x, wid = tid >> 5, lane = tid & 31;
    const int p0 = blockIdx.y * 128, n = blockIdx.z;
    const int warp_m = wid >> 1, warp_p = wid & 1;   // m-dim = p rows here

    float acc[2][4][4];
#pragma unroll
    for (int mi = 0; mi < 2; mi++)
#pragma unroll
        for (int nf = 0; nf < 4; nf++)
#pragma unroll
            for (int q = 0; q < 4; q++) acc[mi][nf][q] = 0.0f;

    const int aRow = warp_m * 32 + (lane & 15);
    const int aCol = (lane >> 4) << 3;
    const int bRow = warp_p * 32 + ((lane >> 4) << 3) + (lane & 7);
    const int bCol = ((lane >> 3) & 1) << 3;
    const uint32_t aBase = smem_u32(sA) + (uint32_t)(aRow * STRZ + aCol) * 2;
    const uint32_t bBase = smem_u32(sB) + (uint32_t)(bRow * STRZ + bCol) * 2;

    for (int kc = 0; kc < 6; kc++) {
        const __nv_bfloat16* A = (kc < 2 || kc >= 4) ? xh : xl;
        const __nv_bfloat16* B = (kc < 4) ? wdh : wdl;
        const int c0 = (kc & 1) * 128;

        __syncthreads();
        for (int idx = tid; idx < 128 * 16; idx += 256) {
            int row = idx >> 4, seg = idx & 15;
            *(uint4*)(sA + row * STRZ + seg * 8) =
                *(const uint4*)(A + ((size_t)(n * HW) + p0 + row) * CIN + c0 + seg * 8);
        }
        for (int idx = tid; idx < 64 * 16; idx += 256) {
            int row = idx >> 4, seg = idx & 15;
            *(uint4*)(sB + row * STRZ + seg * 8) =
                *(const uint4*)(B + row * CIN + c0 + seg * 8);
        }
        __syncthreads();

#pragma unroll
        for (int ks = 0; ks < 8; ks++) {
            uint32_t a0[4], a1[4];
            LDM_X4(a0[0], a0[1], a0[2], a0[3], aBase + (ks * 16) * 2);
            LDM_X4(a1[0], a1[1], a1[2], a1[3], aBase + (16 * STRZ + ks * 16) * 2);
            uint32_t b[2][4];
#pragma unroll
            for (int bi = 0; bi < 2; bi++)
                LDM_X4(b[bi][0], b[bi][1], b[bi][2], b[bi][3],
                       bBase + (bi * 16 * STRZ + ks * 16) * 2);
#pragma unroll
            for (int nf = 0; nf < 4; nf++) {
                int bi = nf >> 1, hp = (nf & 1) << 1;
                MMA_BF16(acc[0][nf], a0, b[bi][hp], b[bi][hp + 1]);
                MMA_BF16(acc[1][nf], a1, b[bi][hp], b[bi][hp + 1]);
            }
        }
    }

    const int er = lane >> 2, ec = (lane & 3) * 2;
#pragma unroll
    for (int mi = 0; mi < 2; mi++) {
        const int pr = p0 + warp_m * 32 + mi * 16 + er;   // global pixel row
#pragma unroll
        for (int nf = 0; nf < 4; nf++) {
            const int mcol = warp_p * 32 + nf * 8 + ec;   // channel 0..63
            float b0 = __ldg(bias + mcol), b1 = __ldg(bias + mcol + 1);
#pragma unroll
            for (int rr = 0; rr < 2; rr++) {
                float v0 = acc[mi][nf][rr * 2 + 0] + b0;
                float v1 = acc[mi][nf][rr * 2 + 1] + b1;
                __nv_bfloat16 h0 = __float2bfloat16(v0);
                __nv_bfloat16 h1 = __float2bfloat16(v1);
                __nv_bfloat162 hv; hv.x = h0; hv.y = h1;
                __nv_bfloat162 lv;
                lv.x = __float2bfloat16(v0 - __bfloat162float(h0));
                lv.y = __float2bfloat16(v1 - __bfloat162float(h1));
                size_t o = ((size_t)(n * HW) + pr + rr * 8) * CM + mcol;
                *(__nv_bfloat162*)(th + o) = hv;
                *(__nv_bfloat162*)(tl + o) = lv;
            }
        }
    }
}

// ---------------------------------------------------------------------------
// e = conv3x3(t) + b_enc as im2col GEMM on tensor cores.
// A = Wenc [128pad][576] (K = tap*64+m), B = im2col(t^T) staged per tap.
// p-tile = 128 px = 2 full image rows (tap gather = row shift, zero borders).
// 27 K-chunks of 64: (Whi,thi), (Whi,tlo), (Wlo,thi) x 9 taps.
// ---------------------------------------------------------------------------
#define STR2 72

__global__ void __launch_bounds__(256) enc_mma(
        const __nv_bfloat16* __restrict__ weh, const __nv_bfloat16* __restrict__ wel,
        const __nv_bfloat16* __restrict__ th, const __nv_bfloat16* __restrict__ tl,
        const float* __restrict__ benc, float* __restrict__ E) {
    extern __shared__ __nv_bfloat16 sm[];
    __nv_bfloat16* sA = sm;               // [128][STR2]
    __nv_bfloat16* sB = sm + 128 * STR2;  // [128][STR2]

    const int tid = threadIdx.x, wid = tid >> 5, lane = tid & 31;
    const int p0 = blockIdx.x * 128, n = blockIdx.z;
    const int r0 = p0 >> 6;               // first image row of tile (2 rows)
    const int warp_m = wid >> 1, warp_p = wid & 1;

    float acc[2][8][4];
#pragma unroll
    for (int mi = 0; mi < 2; mi++)
#pragma unroll
        for (int nf = 0; nf < 8; nf++)
#pragma unroll
            for (int q = 0; q < 4; q++) acc[mi][nf][q] = 0.0f;

    const int aRow = warp_m * 32 + (lane & 15);
    const int aCol = (lane >> 4) << 3;
    const int bRow = warp_p * 64 + ((lane >> 4) << 3) + (lane & 7);
    const int bCol = ((lane >> 3) & 1) << 3;
    const uint32_t aBase = smem_u32(sA) + (uint32_t)(aRow * STR2 + aCol) * 2;
    const uint32_t bBase = smem_u32(sB) + (uint32_t)(bRow * STR2 + bCol) * 2;

    // staging roles: 1024 uint4 units per operand, 4 per thread
    const int srow = tid >> 1;            // covers 128 rows in 2 passes? no:
    // use idx loop instead for clarity

    for (int term = 0; term < 3; term++) {
        const __nv_bfloat16* A = (term < 2) ? weh : wel;
        const __nv_bfloat16* B = (term == 1) ? tl : th;
        for (int tap = 0; tap < 9; tap++) {
            const int ki = tap / 3 - 1, kj = tap % 3 - 1;   // -1..1
            __syncthreads();
            for (int idx = tid; idx < 128 * 8; idx += 256) {
                int row = idx >> 3, seg = idx & 7;
                // A: Wenc rows (q), cols tap*64 + seg*8
                *(uint4*)(sA + row * STR2 + seg * 8) =
                    *(const uint4*)(A + row * 576 + tap * 64 + seg * 8);
                // B: im2col gather
                int hh2 = r0 + (row >> 6) + ki;
                int ww2 = (row & 63) + kj;
                uint4 v = make_uint4(0, 0, 0, 0);
                if ((unsigned)hh2 < HH && (unsigned)ww2 < WW)
                    v = *(const uint4*)(B +
                        ((size_t)(n * HW) + hh2 * WW + ww2) * CM + seg * 8);
                *(uint4*)(sB + row * STR2 + seg * 8) = v;
            }
            __syncthreads();

#pragma unroll
            for (int ks = 0; ks < 4; ks++) {
                uint32_t a0[4], a1[4];
                LDM_X4(a0[0], a0[1], a0[2], a0[3], aBase + (ks * 16) * 2);
                LDM_X4(a1[0], a1[1], a1[2], a1[3],
                       aBase + (16 * STR2 + ks * 16) * 2);
                uint32_t b[4][4];
#pragma unroll
                for (int bi = 0; bi < 4; bi++)
                    LDM_X4(b[bi][0], b[bi][1], b[bi][2], b[bi][3],
                           bBase + (bi * 16 * STR2 + ks * 16) * 2);
#pragma unroll
                for (int nf = 0; nf < 8; nf++) {
                    int bi = nf >> 1, hp = (nf & 1) << 1;
                    MMA_BF16(acc[0][nf], a0, b[bi][hp], b[bi][hp + 1]);
                    MMA_BF16(acc[1][nf], a1, b[bi][hp], b[bi][hp + 1]);
                }
            }
        }
    }

    const int er = lane >> 2, ec = (lane & 3) * 2;
#pragma unroll
    for (int mi = 0; mi < 2; mi++) {
        const int mb = warp_m * 32 + mi * 16 + er;   // q
#pragma unroll
        for (int nf = 0; nf < 8; nf++) {
            const int pcol = p0 + warp_p * 64 + nf * 8 + ec;
            if (mb < EOUT) {
                float b = __ldg(benc + mb);
                *(float2*)(E + ((size_t)(n * EOUT + mb)) * HW + pcol) =
                    make_float2(acc[mi][nf][0] + b, acc[mi][nf][1] + b);
            }
            if (mb + 8 < EOUT) {
                float b = __ldg(benc + mb + 8);
                *(float2*)(E + ((size_t)(n * EOUT + mb + 8)) * HW + pcol) =
                    make_float2(acc[mi][nf][2] + b, acc[mi][nf][3] + b);
            }
        }
    }
}

// ---------------------------------------------------------------------------
// Fused softmax + reassembly + pixel-shuffle + bias (proven R8 version)
// ---------------------------------------------------------------------------
__global__ void __launch_bounds__(256) carafe_kernel(
        const float* __restrict__ E, const float* __restrict__ Z,
        const float* __restrict__ bout, float* __restrict__ out) {
    __shared__ float sZ[2][4 * 5 * 72];

    const int nh = blockIdx.x;
    const int n  = nh >> 6;
    const int h  = nh & 63;
    const int cquart = blockIdx.y;
    const int tid   = threadIdx.x;
    const int w     = tid & 63;
    const int psel  = (tid >> 6) & 1;
    const int cslot = tid >> 7;

    const int p0 = 2 * psel;
    float kr[50];
    const float* eb = E + (size_t)n * EOUT * HW + h * WW + w;
#pragma unroll
    for (int k = 0; k < 25; k++) {
        kr[k * 2 + 0] = eb[(k * 4 + p0 + 0) * HW];
        kr[k * 2 + 1] = eb[(k * 4 + p0 + 1) * HW];
    }
#pragma unroll
    for (int pp = 0; pp < 2; pp++) {
        float mx = kr[pp];
#pragma unroll
        for (int k = 1; k < 25; k++) mx = fmaxf(mx, kr[k * 2 + pp]);
        float s = 0.0f;
#pragma unroll
        for (int k = 0; k < 25; k++) {
            float ex = __expf(kr[k * 2 + pp] - mx);
            kr[k * 2 + pp] = ex;
            s += ex;
        }
        float inv = 1.0f / s;
#pragma unroll
        for (int k = 0; k < 25; k++) kr[k * 2 + pp] *= inv;
    }

    const int lane64 = tid & 63;
    const int sch    = tid >> 6;
    const int hch    = tid >> 5;
    const int t2     = tid & 31;
    float2* op = (float2*)out;

    auto stage = [&](int it, int buf) {
        const int cbase = cquart * 64 + it * 4;
        float4* sZ4 = (float4*)sZ[buf];
        const float4* zc = (const float4*)(Z +
            ((size_t)(n * OUTC + cbase + sch) * HH) * WW);
        int r = lane64 >> 4, g = lane64 & 15;
        int row = h - 2 + r;
        float4 v = make_float4(0.f, 0.f, 0.f, 0.f);
        if ((unsigned)row < HH) v = zc[row * 16 + g];
        sZ4[sch * 90 + r * 18 + 1 + g] = v;
        if (lane64 < 16) {
            int row2 = h + 2;
            float4 v2 = make_float4(0.f, 0.f, 0.f, 0.f);
            if ((unsigned)row2 < HH) v2 = zc[row2 * 16 + lane64];
            sZ4[sch * 90 + 4 * 18 + 1 + lane64] = v2;
        }
        if (tid < 128 && t2 < 20) {
            int rr = t2 >> 2, cc = t2 & 3;
            int hrow = h - 2 + rr;
            int wc = (cc < 2) ? cc - 2 : 62 + cc;
            float hv = 0.0f;
            if ((unsigned)hrow < HH && (unsigned)wc < WW)
                hv = Z[((size_t)(n * OUTC + cbase + hch) * HH + hrow) * WW + wc];
            sZ[buf][hch * 360 + rr * 72 + ((cc < 2) ? cc + 2 : 66 + cc)] = hv;
        }
    };

    stage(0, 0);
    __syncthreads();

    for (int it = 0; it < 16; it++) {
        if (it < 15) stage(it + 1, (it + 1) & 1);

        const int cbase = cquart * 64 + it * 4;
        const int c0 = cbase + 2 * cslot;
        const float* zb = sZ[it & 1] + (2 * cslot) * 360 + (w + 2);
        float a00 = 0.f, a01 = 0.f, a10 = 0.f, a11 = 0.f;
#pragma unroll
        for (int ki = 0; ki < 5; ki++) {
#pragma unroll
            for (int kj = 0; kj < 5; kj++) {
                int kk = ki * 5 + kj;
                float z0 = zb[ki * 72 + kj];
                float z1 = zb[360 + ki * 72 + kj];
                a00 += z0 * kr[kk * 2 + 0];
                a01 += z0 * kr[kk * 2 + 1];
                a10 += z1 * kr[kk * 2 + 0];
                a11 += z1 * kr[kk * 2 + 1];
            }
        }
        float b0 = __ldg(bout + c0), b1 = __ldg(bout + c0 + 1);
        int row = 2 * h + psel;
        op[((n * OUTC + c0    ) * 128 + row) * 64 + w] = make_float2(a00 + b0, a01 + b0);
        op[((n * OUTC + c0 + 1) * 128 + row) * 64 + w] = make_float2(a10 + b1, a11 + b1);
        __syncthreads();
    }
}

// ---------------------------------------------------------------------------
extern "C" void kernel_launch(void* const* d_in, const int* in_sizes, int n_in,
                              void* d_out, int out_size) {
    const float* x  = (const float*)d_in[0];
    const float* Wd = (const float*)d_in[1];
    const float* bd = (const float*)d_in[2];
    const float* We = (const float*)d_in[3];
    const float* be = (const float*)d_in[4];
    const float* Wo = (const float*)d_in[5];
    const float* bo = (const float*)d_in[6];
    float* out = (float*)d_out;

    static float *ge = nullptr, *gz = nullptr;
    static __nv_bfloat16 *gxh, *gxl, *gwh, *gwl, *gwdh, *gwdl,
                         *gth, *gtl, *gweh, *gwel;
    static cudaStream_t s2;
    static cudaEvent_t ev_fork, ev_join;
    const int z_smem = (128 + 128) * STRZ * 2;   // 69632 B
    const int t_smem = (128 + 64) * STRZ * 2;    // 52224 B
    const int e_smem = (128 + 128) * STR2 * 2;   // 36864 B
    if (!ge) {
        cudaGetSymbolAddress((void**)&ge,   g_e);
        cudaGetSymbolAddress((void**)&gz,   g_z);
        cudaGetSymbolAddress((void**)&gxh,  g_xh);
        cudaGetSymbolAddress((void**)&gxl,  g_xl);
        cudaGetSymbolAddress((void**)&gwh,  g_wh);
        cudaGetSymbolAddress((void**)&gwl,  g_wl);
        cudaGetSymbolAddress((void**)&gwdh, g_wdh);
        cudaGetSymbolAddress((void**)&gwdl, g_wdl);
        cudaGetSymbolAddress((void**)&gth,  g_th);
        cudaGetSymbolAddress((void**)&gtl,  g_tl);
        cudaGetSymbolAddress((void**)&gweh, g_weh);
        cudaGetSymbolAddress((void**)&gwel, g_wel);
        cudaStreamCreateWithFlags(&s2, cudaStreamNonBlocking);
        cudaEventCreateWithFlags(&ev_fork, cudaEventDisableTiming);
        cudaEventCreateWithFlags(&ev_join, cudaEventDisableTiming);
        cudaFuncSetAttribute(zgemm_mma,
                             cudaFuncAttributeMaxDynamicSharedMemorySize, z_smem);
        cudaFuncSetAttribute(tgemmT_mma,
                             cudaFuncAttributeMaxDynamicSharedMemorySize, t_smem);
        cudaFuncSetAttribute(enc_mma,
                             cudaFuncAttributeMaxDynamicSharedMemorySize, e_smem);
    }

    // Converts needed by the z fork first
    convert_w_kernel<<<256, 256>>>(Wo, gwh, gwl);
    convert_x_kernel<<<dim3(64, 4, 4), 256>>>(x, gxh, gxl);

    // Fork: z = W_out @ x on tensor cores (s2)
    cudaEventRecord(ev_fork, 0);
    cudaStreamWaitEvent(s2, ev_fork, 0);
    zgemm_mma<<<dim3(32, 2, 4), 256, z_smem, s2>>>(gwh, gwl, gxh, gxl, gz);
    cudaEventRecord(ev_join, s2);

    // Main path: remaining converts, t^T (bf16 hi/lo), enc GEMM
    convert_w_kernel<<<64, 256>>>(Wd, gwdh, gwdl);
    convert_wenc_kernel<<<288, 256>>>(We, gweh, gwel);
    tgemmT_mma<<<dim3(1, 32, 4), 256, t_smem>>>(gxh, gxl, gwdh, gwdl, bd, gth, gtl);
    enc_mma<<<dim3(32, 1, 4), 256, e_smem>>>(gweh, gwel, gth, gtl, be, ge);

    // Join, then fused reassembly.
    cudaStreamWaitEvent(0, ev_join, 0);
    carafe_kernel<<<dim3(256, 4), 256>>>(ge, gz, bo, out);
}

// round 17
// speedup vs baseline: 2.0489x; 1.1971x over previous
#include <cuda_runtime.h>
#include <cuda_bf16.h>
#include <math.h>
#include <stdint.h>

// Shapes (fixed by the problem)
#define NB   4
#define CIN  256
#define HH   64
#define WW   64
#define HW   4096
#define CM   64
#define EOUT 100
#define OUTC 256

typedef unsigned long long u64;

// Scratch (device globals; allocation is forbidden)
__device__ float g_e[NB * EOUT * HW];           // 6.5 MB encoder logits
__device__ float g_z[NB * OUTC * HW];           // 16 MB  z = W_out @ x
__device__ __nv_bfloat16 g_xh[NB * HW * CIN];   // x^T [n][p][c] hi
__device__ __nv_bfloat16 g_xl[NB * HW * CIN];   // lo residual
__device__ __nv_bfloat16 g_wh[OUTC * CIN];      // W_out hi
__device__ __nv_bfloat16 g_wl[OUTC * CIN];      // W_out lo
__device__ __nv_bfloat16 g_wdh[CM * CIN];       // W_down hi
__device__ __nv_bfloat16 g_wdl[CM * CIN];       // W_down lo
__device__ __nv_bfloat16 g_th[NB * HW * CM];    // t^T [n][p][m] hi
__device__ __nv_bfloat16 g_tl[NB * HW * CM];    // t^T lo
__device__ __nv_bfloat16 g_weh[128 * 576];      // Wenc repacked [qpad][tap*64+m] hi
__device__ __nv_bfloat16 g_wel[128 * 576];      // lo

__device__ __forceinline__ uint32_t smem_u32(const void* p) {
    uint32_t a;
    asm("{.reg .u64 t; cvta.to.shared.u64 t, %1; cvt.u32.u64 %0, t;}"
        : "=r"(a) : "l"(p));
    return a;
}

// ---------------------------------------------------------------------------
// Converts
// ---------------------------------------------------------------------------
__global__ void __launch_bounds__(256) convert_w_kernel(
        const float* __restrict__ W,
        __nv_bfloat16* __restrict__ wh, __nv_bfloat16* __restrict__ wl) {
    int idx = blockIdx.x * 256 + threadIdx.x;
    float v = W[idx];
    __nv_bfloat16 h = __float2bfloat16(v);
    wh[idx] = h;
    wl[idx] = __float2bfloat16(v - __bfloat162float(h));
}

// Wenc [100][64][3][3] fp32 -> [128 pad][tap*64+m] bf16 hi/lo
__global__ void __launch_bounds__(256) convert_wenc_kernel(
        const float* __restrict__ W,
        __nv_bfloat16* __restrict__ wh, __nv_bfloat16* __restrict__ wl) {
    int idx = blockIdx.x * 256 + threadIdx.x;   // 128*576 = 73728
    if (idx >= 128 * 576) return;
    int q = idx / 576, k = idx % 576;
    int tap = k >> 6, m = k & 63;
    float v = (q < EOUT) ? W[(q * CM + m) * 9 + tap] : 0.0f;
    __nv_bfloat16 h = __float2bfloat16(v);
    wh[idx] = h;
    wl[idx] = __float2bfloat16(v - __bfloat162float(h));
}

// x: [n][c][p] fp32 -> [n][p][c] bf16 hi/lo (64x64 transpose tiles)
__global__ void __launch_bounds__(256) convert_x_kernel(
        const float* __restrict__ X,
        __nv_bfloat16* __restrict__ xh, __nv_bfloat16* __restrict__ xl) {
    __shared__ float st[64][65];
    const int tid = threadIdx.x;
    const int pt = blockIdx.x * 64, ct = blockIdx.y * 64, n = blockIdx.z;
#pragma unroll
    for (int i = 0; i < 16; i++) {
        int linear = tid + i * 256;
        int p = linear & 63, c = linear >> 6;
        st[c][p] = X[((size_t)(n * CIN + ct + c)) * HW + pt + p];
    }
    __syncthreads();
    int p = tid >> 2, cs = (tid & 3) * 16;
    size_t ob = ((size_t)(n * HW + pt + p)) * CIN + ct + cs;
#pragma unroll
    for (int k = 0; k < 16; k++) {
        float v = st[cs + k][p];
        __nv_bfloat16 h = __float2bfloat16(v);
        xh[ob + k] = h;
        xl[ob + k] = __float2bfloat16(v - __bfloat162float(h));
    }
}

// ---------------------------------------------------------------------------
// MMA primitives (fragment layout VERIFIED on HW in R11/R14/R15)
// ---------------------------------------------------------------------------
#define STRZ 136   // smem row stride (bf16) for z / tT tiles

#define LDM_X4(r0, r1, r2, r3, addr) \
    asm volatile("ldmatrix.sync.aligned.m8n8.x4.shared.b16 {%0,%1,%2,%3}, [%4];" \
        : "=r"(r0), "=r"(r1), "=r"(r2), "=r"(r3) : "r"(addr))

#define MMA_BF16(d, a, b0v, b1v) \
    asm volatile("mma.sync.aligned.m16n8k16.row.col.f32.bf16.bf16.f32 " \
        "{%0,%1,%2,%3},{%4,%5,%6,%7},{%8,%9},{%0,%1,%2,%3};" \
        : "+f"((d)[0]), "+f"((d)[1]), "+f"((d)[2]), "+f"((d)[3]) \
        : "r"((a)[0]), "r"((a)[1]), "r"((a)[2]), "r"((a)[3]), \
          "r"(b0v), "r"(b1v))

// ---------------------------------------------------------------------------
// z = W_out @ x  (unchanged — measured 27 us, tensor 38.7%)
// ---------------------------------------------------------------------------
__global__ void __launch_bounds__(256) zgemm_mma(
        const __nv_bfloat16* __restrict__ ah, const __nv_bfloat16* __restrict__ al,
        const __nv_bfloat16* __restrict__ bh, const __nv_bfloat16* __restrict__ bl,
        float* __restrict__ Out) {
    extern __shared__ __nv_bfloat16 sm[];
    __nv_bfloat16* sA = sm;                 // [128][STRZ]
    __nv_bfloat16* sB = sm + 128 * STRZ;    // [128][STRZ]

    const int tid = threadIdx.x, wid = tid >> 5, lane = tid & 31;
    const int p0 = blockIdx.x * 128, m0 = blockIdx.y * 128, n = blockIdx.z;
    const int warp_m = wid >> 1, warp_p = wid & 1;

    float acc[2][8][4];
#pragma unroll
    for (int mi = 0; mi < 2; mi++)
#pragma unroll
        for (int nf = 0; nf < 8; nf++)
#pragma unroll
            for (int q = 0; q < 4; q++) acc[mi][nf][q] = 0.0f;

    const int aRow = warp_m * 32 + (lane & 15);
    const int aCol = (lane >> 4) << 3;
    const int bRow = warp_p * 64 + ((lane >> 4) << 3) + (lane & 7);
    const int bCol = ((lane >> 3) & 1) << 3;
    const uint32_t aBase = smem_u32(sA) + (uint32_t)(aRow * STRZ + aCol) * 2;
    const uint32_t bBase = smem_u32(sB) + (uint32_t)(bRow * STRZ + bCol) * 2;

    for (int kc = 0; kc < 6; kc++) {
        const __nv_bfloat16* A = (kc < 4) ? ah : al;
        const __nv_bfloat16* B = (kc < 2 || kc >= 4) ? bh : bl;
        const int c0 = (kc & 1) * 128;

        __syncthreads();
        for (int idx = tid; idx < 128 * 16; idx += 256) {
            int row = idx >> 4, seg = idx & 15;
            *(uint4*)(sA + row * STRZ + seg * 8) =
                *(const uint4*)(A + (m0 + row) * CIN + c0 + seg * 8);
            *(uint4*)(sB + row * STRZ + seg * 8) =
                *(const uint4*)(B + ((size_t)(n * HW) + p0 + row) * CIN + c0 + seg * 8);
        }
        __syncthreads();

#pragma unroll
        for (int ks = 0; ks < 8; ks++) {
            uint32_t a0[4], a1[4];
            LDM_X4(a0[0], a0[1], a0[2], a0[3], aBase + (ks * 16) * 2);
            LDM_X4(a1[0], a1[1], a1[2], a1[3], aBase + (16 * STRZ + ks * 16) * 2);
            uint32_t b[4][4];
#pragma unroll
            for (int bi = 0; bi < 4; bi++)
                LDM_X4(b[bi][0], b[bi][1], b[bi][2], b[bi][3],
                       bBase + (bi * 16 * STRZ + ks * 16) * 2);
#pragma unroll
            for (int nf = 0; nf < 8; nf++) {
                int bi = nf >> 1, hp = (nf & 1) << 1;
                MMA_BF16(acc[0][nf], a0, b[bi][hp], b[bi][hp + 1]);
                MMA_BF16(acc[1][nf], a1, b[bi][hp], b[bi][hp + 1]);
            }
        }
    }

    const int er = lane >> 2, ec = (lane & 3) * 2;
#pragma unroll
    for (int mi = 0; mi < 2; mi++) {
        const int mb = m0 + warp_m * 32 + mi * 16 + er;
#pragma unroll
        for (int nf = 0; nf < 8; nf++) {
            const int pcol = p0 + warp_p * 64 + nf * 8 + ec;
            float* z0 = Out + ((size_t)(n * OUTC + mb)) * HW + pcol;
            *(float2*)z0 = make_float2(acc[mi][nf][0], acc[mi][nf][1]);
            *(float2*)(z0 + 8 * HW) = make_float2(acc[mi][nf][2], acc[mi][nf][3]);
        }
    }
}

// ---------------------------------------------------------------------------
// t^T = (W_down @ x)^T + b_down, output bf16 hi/lo [n][p][64]. (unchanged)
// ---------------------------------------------------------------------------
__global__ void __launch_bounds__(256) tgemmT_mma(
        const __nv_bfloat16* __restrict__ xh, const __nv_bfloat16* __restrict__ xl,
        const __nv_bfloat16* __restrict__ wdh, const __nv_bfloat16* __restrict__ wdl,
        const float* __restrict__ bias,
        __nv_bfloat16* __restrict__ th, __nv_bfloat16* __restrict__ tl) {
    extern __shared__ __nv_bfloat16 sm[];
    __nv_bfloat16* sA = sm;                 // [128][STRZ]  x^T
    __nv_bfloat16* sB = sm + 128 * STRZ;    // [64][STRZ]   W_down

    const int tid = threadIdx.x, wid = tid >> 5, lane = tid & 31;
    const int p0 = blockIdx.y * 128, n = blockIdx.z;
    const int warp_m = wid >> 1, warp_p = wid & 1;

    float acc[2][4][4];
#pragma unroll
    for (int mi = 0; mi < 2; mi++)
#pragma unroll
        for (int nf = 0; nf < 4; nf++)
#pragma unroll
            for (int q = 0; q < 4; q++) acc[mi][nf][q] = 0.0f;

    const int aRow = warp_m * 32 + (lane & 15);
    const int aCol = (lane >> 4) << 3;
    const int bRow = warp_p * 32 + ((lane >> 4) << 3) + (lane & 7);
    const int bCol = ((lane >> 3) & 1) << 3;
    const uint32_t aBase = smem_u32(sA) + (uint32_t)(aRow * STRZ + aCol) * 2;
    const uint32_t bBase = smem_u32(sB) + (uint32_t)(bRow * STRZ + bCol) * 2;

    for (int kc = 0; kc < 6; kc++) {
        const __nv_bfloat16* A = (kc < 2 || kc >= 4) ? xh : xl;
        const __nv_bfloat16* B = (kc < 4) ? wdh : wdl;
        const int c0 = (kc & 1) * 128;

        __syncthreads();
        for (int idx = tid; idx < 128 * 16; idx += 256) {
            int row = idx >> 4, seg = idx & 15;
            *(uint4*)(sA + row * STRZ + seg * 8) =
                *(const uint4*)(A + ((size_t)(n * HW) + p0 + row) * CIN + c0 + seg * 8);
        }
        for (int idx = tid; idx < 64 * 16; idx += 256) {
            int row = idx >> 4, seg = idx & 15;
            *(uint4*)(sB + row * STRZ + seg * 8) =
                *(const uint4*)(B + row * CIN + c0 + seg * 8);
        }
        __syncthreads();

#pragma unroll
        for (int ks = 0; ks < 8; ks++) {
            uint32_t a0[4], a1[4];
            LDM_X4(a0[0], a0[1], a0[2], a0[3], aBase + (ks * 16) * 2);
            LDM_X4(a1[0], a1[1], a1[2], a1[3], aBase + (16 * STRZ + ks * 16) * 2);
            uint32_t b[2][4];
#pragma unroll
            for (int bi = 0; bi < 2; bi++)
                LDM_X4(b[bi][0], b[bi][1], b[bi][2], b[bi][3],
                       bBase + (bi * 16 * STRZ + ks * 16) * 2);
#pragma unroll
            for (int nf = 0; nf < 4; nf++) {
                int bi = nf >> 1, hp = (nf & 1) << 1;
                MMA_BF16(acc[0][nf], a0, b[bi][hp], b[bi][hp + 1]);
                MMA_BF16(acc[1][nf], a1, b[bi][hp], b[bi][hp + 1]);
            }
        }
    }

    const int er = lane >> 2, ec = (lane & 3) * 2;
#pragma unroll
    for (int mi = 0; mi < 2; mi++) {
        const int pr = p0 + warp_m * 32 + mi * 16 + er;
#pragma unroll
        for (int nf = 0; nf < 4; nf++) {
            const int mcol = warp_p * 32 + nf * 8 + ec;
            float b0 = __ldg(bias + mcol), b1 = __ldg(bias + mcol + 1);
#pragma unroll
            for (int rr = 0; rr < 2; rr++) {
                float v0 = acc[mi][nf][rr * 2 + 0] + b0;
                float v1 = acc[mi][nf][rr * 2 + 1] + b1;
                __nv_bfloat16 h0 = __float2bfloat16(v0);
                __nv_bfloat16 h1 = __float2bfloat16(v1);
                __nv_bfloat162 hv; hv.x = h0; hv.y = h1;
                __nv_bfloat162 lv;
                lv.x = __float2bfloat16(v0 - __bfloat162float(h0));
                lv.y = __float2bfloat16(v1 - __bfloat162float(h1));
                size_t o = ((size_t)(n * HW) + pr + rr * 8) * CM + mcol;
                *(__nv_bfloat162*)(th + o) = hv;
                *(__nv_bfloat162*)(tl + o) = lv;
            }
        }
    }
}

// ---------------------------------------------------------------------------
// e = conv3x3(t) + b_enc as im2col GEMM, split-terms MERGED:
// per tap stage Ahi/Alo/Bhi/Blo together (72 KB smem), then do
// Ahi@Bhi + Ahi@Blo + Alo@Bhi in one pass.  9 sync rounds instead of 27,
// 36 tile-stages instead of 54, same MMA count.
// ---------------------------------------------------------------------------
#define STR2 72

__global__ void __launch_bounds__(256) enc_mma(
        const __nv_bfloat16* __restrict__ weh, const __nv_bfloat16* __restrict__ wel,
        const __nv_bfloat16* __restrict__ th, const __nv_bfloat16* __restrict__ tl,
        const float* __restrict__ benc, float* __restrict__ E) {
    extern __shared__ __nv_bfloat16 sm[];
    __nv_bfloat16* sAh = sm;                  // [128][STR2]
    __nv_bfloat16* sAl = sm + 128 * STR2;
    __nv_bfloat16* sBh = sm + 2 * 128 * STR2;
    __nv_bfloat16* sBl = sm + 3 * 128 * STR2;

    const int tid = threadIdx.x, wid = tid >> 5, lane = tid & 31;
    const int p0 = blockIdx.x * 128, n = blockIdx.z;
    const int r0 = p0 >> 6;                   // first image row (tile = 2 rows)
    const int warp_m = wid >> 1, warp_p = wid & 1;

    float acc[2][8][4];
#pragma unroll
    for (int mi = 0; mi < 2; mi++)
#pragma unroll
        for (int nf = 0; nf < 8; nf++)
#pragma unroll
            for (int q = 0; q < 4; q++) acc[mi][nf][q] = 0.0f;

    const int aRow = warp_m * 32 + (lane & 15);
    const int aCol = (lane >> 4) << 3;
    const int bRow = warp_p * 64 + ((lane >> 4) << 3) + (lane & 7);
    const int bCol = ((lane >> 3) & 1) << 3;
    const uint32_t ahB = smem_u32(sAh) + (uint32_t)(aRow * STR2 + aCol) * 2;
    const uint32_t alB = smem_u32(sAl) + (uint32_t)(aRow * STR2 + aCol) * 2;
    const uint32_t bhB = smem_u32(sBh) + (uint32_t)(bRow * STR2 + bCol) * 2;
    const uint32_t blB = smem_u32(sBl) + (uint32_t)(bRow * STR2 + bCol) * 2;

    for (int tap = 0; tap < 9; tap++) {
        const int ki = tap / 3 - 1, kj = tap % 3 - 1;
        __syncthreads();
        for (int idx = tid; idx < 128 * 8; idx += 256) {
            int row = idx >> 3, seg = idx & 7;
            uint32_t soff = row * STR2 + seg * 8;
            size_t aoff = row * 576 + tap * 64 + seg * 8;
            *(uint4*)(sAh + soff) = *(const uint4*)(weh + aoff);
            *(uint4*)(sAl + soff) = *(const uint4*)(wel + aoff);
            int hh2 = r0 + (row >> 6) + ki;
            int ww2 = (row & 63) + kj;
            uint4 vh = make_uint4(0, 0, 0, 0), vl = make_uint4(0, 0, 0, 0);
            if ((unsigned)hh2 < HH && (unsigned)ww2 < WW) {
                size_t boff = ((size_t)(n * HW) + hh2 * WW + ww2) * CM + seg * 8;
                vh = *(const uint4*)(th + boff);
                vl = *(const uint4*)(tl + boff);
            }
            *(uint4*)(sBh + soff) = vh;
            *(uint4*)(sBl + soff) = vl;
        }
        __syncthreads();

#pragma unroll
        for (int ks = 0; ks < 4; ks++) {
            uint32_t ah0[4], ah1[4], al0[4], al1[4];
            LDM_X4(ah0[0], ah0[1], ah0[2], ah0[3], ahB + (ks * 16) * 2);
            LDM_X4(ah1[0], ah1[1], ah1[2], ah1[3], ahB + (16 * STR2 + ks * 16) * 2);
            LDM_X4(al0[0], al0[1], al0[2], al0[3], alB + (ks * 16) * 2);
            LDM_X4(al1[0], al1[1], al1[2], al1[3], alB + (16 * STR2 + ks * 16) * 2);
#pragma unroll
            for (int bi = 0; bi < 4; bi++) {
                uint32_t bh[4], bl[4];
                LDM_X4(bh[0], bh[1], bh[2], bh[3],
                       bhB + (bi * 16 * STR2 + ks * 16) * 2);
                LDM_X4(bl[0], bl[1], bl[2], bl[3],
                       blB + (bi * 16 * STR2 + ks * 16) * 2);
#pragma unroll
                for (int half = 0; half < 2; half++) {
                    int nf = bi * 2 + half, hp = half << 1;
                    MMA_BF16(acc[0][nf], ah0, bh[hp], bh[hp + 1]);
                    MMA_BF16(acc[1][nf], ah1, bh[hp], bh[hp + 1]);
                    MMA_BF16(acc[0][nf], ah0, bl[hp], bl[hp + 1]);
                    MMA_BF16(acc[1][nf], ah1, bl[hp], bl[hp + 1]);
                    MMA_BF16(acc[0][nf], al0, bh[hp], bh[hp + 1]);
                    MMA_BF16(acc[1][nf], al1, bh[hp], bh[hp + 1]);
                }
            }
        }
    }

    const int er = lane >> 2, ec = (lane & 3) * 2;
#pragma unroll
    for (int mi = 0; mi < 2; mi++) {
        const int mb = warp_m * 32 + mi * 16 + er;   // q
#pragma unroll
        for (int nf = 0; nf < 8; nf++) {
            const int pcol = p0 + warp_p * 64 + nf * 8 + ec;
            if (mb < EOUT) {
                float b = __ldg(benc + mb);
                *(float2*)(E + ((size_t)(n * EOUT + mb)) * HW + pcol) =
                    make_float2(acc[mi][nf][0] + b, acc[mi][nf][1] + b);
            }
            if (mb + 8 < EOUT) {
                float b = __ldg(benc + mb + 8);
                *(float2*)(E + ((size_t)(n * EOUT + mb + 8)) * HW + pcol) =
                    make_float2(acc[mi][nf][2] + b, acc[mi][nf][3] + b);
            }
        }
    }
}

// ---------------------------------------------------------------------------
// Fused softmax + reassembly + pixel-shuffle + bias (proven R8 version)
// ---------------------------------------------------------------------------
__global__ void __launch_bounds__(256) carafe_kernel(
        const float* __restrict__ E, const float* __restrict__ Z,
        const float* __restrict__ bout, float* __restrict__ out) {
    __shared__ float sZ[2][4 * 5 * 72];

    const int nh = blockIdx.x;
    const int n  = nh >> 6;
    const int h  = nh & 63;
    const int cquart = blockIdx.y;
    const int tid   = threadIdx.x;
    const int w     = tid & 63;
    const int psel  = (tid >> 6) & 1;
    const int cslot = tid >> 7;

    const int p0 = 2 * psel;
    float kr[50];
    const float* eb = E + (size_t)n * EOUT * HW + h * WW + w;
#pragma unroll
    for (int k = 0; k < 25; k++) {
        kr[k * 2 + 0] = eb[(k * 4 + p0 + 0) * HW];
        kr[k * 2 + 1] = eb[(k * 4 + p0 + 1) * HW];
    }
#pragma unroll
    for (int pp = 0; pp < 2; pp++) {
        float mx = kr[pp];
#pragma unroll
        for (int k = 1; k < 25; k++) mx = fmaxf(mx, kr[k * 2 + pp]);
        float s = 0.0f;
#pragma unroll
        for (int k = 0; k < 25; k++) {
            float ex = __expf(kr[k * 2 + pp] - mx);
            kr[k * 2 + pp] = ex;
            s += ex;
        }
        float inv = 1.0f / s;
#pragma unroll
        for (int k = 0; k < 25; k++) kr[k * 2 + pp] *= inv;
    }

    const int lane64 = tid & 63;
    const int sch    = tid >> 6;
    const int hch    = tid >> 5;
    const int t2     = tid & 31;
    float2* op = (float2*)out;

    auto stage = [&](int it, int buf) {
        const int cbase = cquart * 64 + it * 4;
        float4* sZ4 = (float4*)sZ[buf];
        const float4* zc = (const float4*)(Z +
            ((size_t)(n * OUTC + cbase + sch) * HH) * WW);
        int r = lane64 >> 4, g = lane64 & 15;
        int row = h - 2 + r;
        float4 v = make_float4(0.f, 0.f, 0.f, 0.f);
        if ((unsigned)row < HH) v = zc[row * 16 + g];
        sZ4[sch * 90 + r * 18 + 1 + g] = v;
        if (lane64 < 16) {
            int row2 = h + 2;
            float4 v2 = make_float4(0.f, 0.f, 0.f, 0.f);
            if ((unsigned)row2 < HH) v2 = zc[row2 * 16 + lane64];
            sZ4[sch * 90 + 4 * 18 + 1 + lane64] = v2;
        }
        if (tid < 128 && t2 < 20) {
            int rr = t2 >> 2, cc = t2 & 3;
            int hrow = h - 2 + rr;
            int wc = (cc < 2) ? cc - 2 : 62 + cc;
            float hv = 0.0f;
            if ((unsigned)hrow < HH && (unsigned)wc < WW)
                hv = Z[((size_t)(n * OUTC + cbase + hch) * HH + hrow) * WW + wc];
            sZ[buf][hch * 360 + rr * 72 + ((cc < 2) ? cc + 2 : 66 + cc)] = hv;
        }
    };

    stage(0, 0);
    __syncthreads();

    for (int it = 0; it < 16; it++) {
        if (it < 15) stage(it + 1, (it + 1) & 1);

        const int cbase = cquart * 64 + it * 4;
        const int c0 = cbase + 2 * cslot;
        const float* zb = sZ[it & 1] + (2 * cslot) * 360 + (w + 2);
        float a00 = 0.f, a01 = 0.f, a10 = 0.f, a11 = 0.f;
#pragma unroll
        for (int ki = 0; ki < 5; ki++) {
#pragma unroll
            for (int kj = 0; kj < 5; kj++) {
                int kk = ki * 5 + kj;
                float z0 = zb[ki * 72 + kj];
                float z1 = zb[360 + ki * 72 + kj];
                a00 += z0 * kr[kk * 2 + 0];
                a01 += z0 * kr[kk * 2 + 1];
                a10 += z1 * kr[kk * 2 + 0];
                a11 += z1 * kr[kk * 2 + 1];
            }
        }
        float b0 = __ldg(bout + c0), b1 = __ldg(bout + c0 + 1);
        int row = 2 * h + psel;
        op[((n * OUTC + c0    ) * 128 + row) * 64 + w] = make_float2(a00 + b0, a01 + b0);
        op[((n * OUTC + c0 + 1) * 128 + row) * 64 + w] = make_float2(a10 + b1, a11 + b1);
        __syncthreads();
    }
}

// ---------------------------------------------------------------------------
extern "C" void kernel_launch(void* const* d_in, const int* in_sizes, int n_in,
                              void* d_out, int out_size) {
    const float* x  = (const float*)d_in[0];
    const float* Wd = (const float*)d_in[1];
    const float* bd = (const float*)d_in[2];
    const float* We = (const float*)d_in[3];
    const float* be = (const float*)d_in[4];
    const float* Wo = (const float*)d_in[5];
    const float* bo = (const float*)d_in[6];
    float* out = (float*)d_out;

    static float *ge = nullptr, *gz = nullptr;
    static __nv_bfloat16 *gxh, *gxl, *gwh, *gwl, *gwdh, *gwdl,
                         *gth, *gtl, *gweh, *gwel;
    static cudaStream_t s2;
    static cudaEvent_t ev_fork, ev_w, ev_x, ev_join;
    const int z_smem = (128 + 128) * STRZ * 2;   // 69632 B
    const int t_smem = (128 + 64) * STRZ * 2;    // 52224 B
    const int e_smem = 4 * 128 * STR2 * 2;       // 73728 B
    if (!ge) {
        cudaGetSymbolAddress((void**)&ge,   g_e);
        cudaGetSymbolAddress((void**)&gz,   g_z);
        cudaGetSymbolAddress((void**)&gxh,  g_xh);
        cudaGetSymbolAddress((void**)&gxl,  g_xl);
        cudaGetSymbolAddress((void**)&gwh,  g_wh);
        cudaGetSymbolAddress((void**)&gwl,  g_wl);
        cudaGetSymbolAddress((void**)&gwdh, g_wdh);
        cudaGetSymbolAddress((void**)&gwdl, g_wdl);
        cudaGetSymbolAddress((void**)&gth,  g_th);
        cudaGetSymbolAddress((void**)&gtl,  g_tl);
        cudaGetSymbolAddress((void**)&gweh, g_weh);
        cudaGetSymbolAddress((void**)&gwel, g_wel);
        cudaStreamCreateWithFlags(&s2, cudaStreamNonBlocking);
        cudaEventCreateWithFlags(&ev_fork, cudaEventDisableTiming);
        cudaEventCreateWithFlags(&ev_w, cudaEventDisableTiming);
        cudaEventCreateWithFlags(&ev_x, cudaEventDisableTiming);
        cudaEventCreateWithFlags(&ev_join, cudaEventDisableTiming);
        cudaFuncSetAttribute(zgemm_mma,
                             cudaFuncAttributeMaxDynamicSharedMemorySize, z_smem);
        cudaFuncSetAttribute(tgemmT_mma,
                             cudaFuncAttributeMaxDynamicSharedMemorySize, t_smem);
        cudaFuncSetAttribute(enc_mma,
                             cudaFuncAttributeMaxDynamicSharedMemorySize, e_smem);
    }

    // Fork s2 from the capture stream FIRST (required for graph capture),
    // then run all weight converts on s2, overlapped with convert_x on main.
    cudaEventRecord(ev_fork, 0);
    cudaStreamWaitEvent(s2, ev_fork, 0);
    convert_w_kernel<<<256, 256, 0, s2>>>(Wo, gwh, gwl);
    convert_w_kernel<<<64, 256, 0, s2>>>(Wd, gwdh, gwdl);
    convert_wenc_kernel<<<288, 256, 0, s2>>>(We, gweh, gwel);
    cudaEventRecord(ev_w, s2);

    // main: x convert
    convert_x_kernel<<<dim3(64, 4, 4), 256>>>(x, gxh, gxl);
    cudaEventRecord(ev_x, 0);

    // s2: z = W_out @ x (needs x)
    cudaStreamWaitEvent(s2, ev_x, 0);
    zgemm_mma<<<dim3(32, 2, 4), 256, z_smem, s2>>>(gwh, gwl, gxh, gxl, gz);
    cudaEventRecord(ev_join, s2);

    // main: t^T (needs Wd from s2), then enc GEMM (needs Wenc from s2)
    cudaStreamWaitEvent(0, ev_w, 0);
    tgemmT_mma<<<dim3(1, 32, 4), 256, t_smem>>>(gxh, gxl, gwdh, gwdl, bd, gth, gtl);
    enc_mma<<<dim3(32, 1, 4), 256, e_smem>>>(gweh, gwel, gth, gtl, be, ge);

    // Join, then fused reassembly.
    cudaStreamWaitEvent(0, ev_join, 0);
    carafe_kernel<<<dim3(256, 4), 256>>>(ge, gz, bo, out);
}